// round 1
// baseline (speedup 1.0000x reference)
#include <cuda_runtime.h>
#include <math.h>

// ---------------- problem constants ----------------
#define S_SEQ   16
#define HID     256
#define INDIM   512
#define DSTATE  64
#define NLAYER  6
#define NCLS    40
#define FF      512
#define EPSV    1e-5f

// ---------------- kernel config --------------------
#define BT        2                 // batch elements per CTA
#define MROWS     (BT*S_SEQ)        // 32 rows
#define NTHREADS  512
#define LDT       36                // padded M-stride of transposed smem tiles

// smem float offsets
#define OFF_XS   0                          // [MROWS][HID] residual, row-major
#define OFF_GS   (OFF_XS + MROWS*HID)       // [MROWS][HID] gate / final-LN
#define OFF_YT   (OFF_GS + MROWS*HID)       // [HID][LDT]  LN output (transposed)
#define OFF_MID  (OFF_YT + HID*LDT)         // [FF][LDT]   data-T / ffn mid (transposed)
#define OFF_AB   (OFF_MID + FF*LDT)         // at[DSTATE][LDT], btt[DSTATE][LDT]
#define OFF_RED  (OFF_AB + 2*DSTATE*LDT)    // head scratch
#define SMEM_FLOATS (OFF_RED + 1024)

typedef unsigned long long ull;

__device__ __forceinline__ ull ffma2(ull a, ull b, ull c) {
    ull d;
    asm("fma.rn.f32x2 %0, %1, %2, %3;" : "=l"(d) : "l"(a), "l"(b), "l"(c));
    return d;
}
__device__ __forceinline__ ull bcast2(float x) {
    ull r;
    asm("mov.b64 %0, {%1, %1};" : "=l"(r) : "f"(x));
    return r;
}
__device__ __forceinline__ float2 unpack2(ull v) {
    float2 r;
    asm("mov.b64 {%0, %1}, %2;" : "=f"(r.x), "=f"(r.y) : "l"(v));
    return r;
}
__device__ __forceinline__ float gelu_exact(float x) {
    return 0.5f * x * (1.0f + erff(x * 0.70710678118654752f));
}

// out[j] = sum_k inT[k][m0+j] * wrow[k]   for j in [0,RPT)
// inT is [K][LDT] transposed smem tile; wrow is a global weight row (K floats, 16B aligned)
template<int K, int RPT>
__device__ __forceinline__ void gemm_col(const float* __restrict__ wrow,
                                         const float* __restrict__ inT,
                                         int m0, float* __restrict__ out)
{
    ull acc[RPT/2];
#pragma unroll
    for (int i = 0; i < RPT/2; ++i) acc[i] = 0ull;
#pragma unroll 4
    for (int k = 0; k < K; k += 4) {
        float4 wv = __ldg(reinterpret_cast<const float4*>(wrow + k));
        float wk[4] = {wv.x, wv.y, wv.z, wv.w};
#pragma unroll
        for (int kk = 0; kk < 4; ++kk) {
            ull wb = bcast2(wk[kk]);
            const ulonglong2* p =
                reinterpret_cast<const ulonglong2*>(inT + (k + kk)*LDT + m0);
#pragma unroll
            for (int j = 0; j < RPT/4; ++j) {
                ulonglong2 v = p[j];
                acc[2*j]     = ffma2(v.x, wb, acc[2*j]);
                acc[2*j + 1] = ffma2(v.y, wb, acc[2*j + 1]);
            }
        }
    }
#pragma unroll
    for (int j = 0; j < RPT/2; ++j) {
        float2 f = unpack2(acc[j]);
        out[2*j] = f.x; out[2*j + 1] = f.y;
    }
}

// LayerNorm of xs[MROWS][HID]. 16 lanes per row (2 rows per warp).
// TRANS: write dst[(h)*LDT + m], else dst[m*HID + h].
template<bool TRANS>
__device__ __forceinline__ void layer_norm(const float* __restrict__ xs,
                                           float* __restrict__ dst,
                                           const float* __restrict__ gw,
                                           const float* __restrict__ bw,
                                           int tid)
{
    int warp = tid >> 5, lane = tid & 31;
    int m   = warp*2 + (lane >> 4);
    int sub = lane & 15;
    const float* row = xs + m*HID + sub*16;
    float v[16];
#pragma unroll
    for (int i = 0; i < 4; ++i) {
        float4 t = *reinterpret_cast<const float4*>(row + i*4);
        v[4*i] = t.x; v[4*i+1] = t.y; v[4*i+2] = t.z; v[4*i+3] = t.w;
    }
    float s = 0.f;
#pragma unroll
    for (int i = 0; i < 16; ++i) s += v[i];
#pragma unroll
    for (int o = 8; o >= 1; o >>= 1) s += __shfl_xor_sync(0xffffffffu, s, o);
    float mean = s * (1.0f/HID);
    float q = 0.f;
#pragma unroll
    for (int i = 0; i < 16; ++i) { float d = v[i] - mean; q += d*d; }
#pragma unroll
    for (int o = 8; o >= 1; o >>= 1) q += __shfl_xor_sync(0xffffffffu, q, o);
    float rstd = rsqrtf(q * (1.0f/HID) + EPSV);
    int h0 = sub*16;
#pragma unroll
    for (int i = 0; i < 16; ++i) {
        float y = (v[i] - mean) * rstd * gw[h0+i] + bw[h0+i];
        if (TRANS) dst[(h0+i)*LDT + m] = y;
        else       dst[m*HID + h0 + i] = y;
    }
}

__global__ void __launch_bounds__(NTHREADS, 1)
mamba_fused_kernel(const float* __restrict__ data,
                   const float* __restrict__ in_w,  const float* __restrict__ in_b,
                   const float* __restrict__ norm_g,const float* __restrict__ norm_b,
                   const float* __restrict__ A_w,   const float* __restrict__ B_w,
                   const float* __restrict__ C_w,
                   const float* __restrict__ D_w,   const float* __restrict__ D_b,
                   const float* __restrict__ gate_w,const float* __restrict__ gate_b,
                   const float* __restrict__ ffn_w1,const float* __restrict__ ffn_b1,
                   const float* __restrict__ ffn_w2,const float* __restrict__ ffn_b2,
                   const float* __restrict__ fln_g, const float* __restrict__ fln_b,
                   const float* __restrict__ out_w, const float* __restrict__ out_b,
                   const float* __restrict__ cls_w, const float* __restrict__ cls_b,
                   const float* __restrict__ attn_w,const float* __restrict__ attn_b,
                   float* __restrict__ out)
{
    extern __shared__ float sm[];
    float* xs  = sm + OFF_XS;
    float* gs  = sm + OFF_GS;
    float* yt  = sm + OFF_YT;
    float* mid = sm + OFF_MID;
    float* at  = sm + OFF_AB;
    float* btt = at + DSTATE*LDT;
    float* red = sm + OFF_RED;

    const int tid = threadIdx.x;
    const int b0  = blockIdx.x * BT;

    // ---- load input rows [32][512] transposed into mid (as datat[k][m]) ----
    {
        const float4* gdat4 =
            reinterpret_cast<const float4*>(data + (size_t)b0 * S_SEQ * INDIM);
#pragma unroll
        for (int i = 0; i < (MROWS*INDIM/4)/NTHREADS; ++i) {
            int idx = tid + i*NTHREADS;
            float4 v = __ldg(gdat4 + idx);
            int lin = idx * 4;
            int m = lin >> 9;          // /512
            int k = lin & (INDIM-1);
            mid[(k+0)*LDT + m] = v.x;
            mid[(k+1)*LDT + m] = v.y;
            mid[(k+2)*LDT + m] = v.z;
            mid[(k+3)*LDT + m] = v.w;
        }
    }
    __syncthreads();

    const int c    = tid & 255;
    const int half = tid >> 8;
    const int m0   = half * 16;

    // ---- input projection: xs = data @ in_w.T + in_b ----
    {
        float o[16];
        gemm_col<INDIM,16>(in_w + c*INDIM, mid, m0, o);
        float bias = in_b[c];
#pragma unroll
        for (int j = 0; j < 16; ++j) xs[(m0+j)*HID + c] = o[j] + bias;
    }
    __syncthreads();

    // ---------------- 6 layers ----------------
    for (int l = 0; l < NLAYER; ++l) {
        const float* ng = norm_g + l*HID;
        const float* nb = norm_b + l*HID;

        layer_norm<true>(xs, yt, ng, nb, tid);
        __syncthreads();

        // gate = sigmoid(y @ gate_w.T + gate_b)
        {
            float o[16];
            gemm_col<HID,16>(gate_w + l*HID*HID + c*HID, yt, m0, o);
            float bias = gate_b[l*HID + c];
#pragma unroll
            for (int j = 0; j < 16; ++j)
                gs[(m0+j)*HID + c] = 1.0f / (1.0f + expf(-(o[j] + bias)));
        }
        // dt = y @ D_w.T + D_b ; xs += dt * (1 - g)   (same-thread gs, no sync needed)
        {
            float o[16];
            gemm_col<HID,16>(D_w + l*HID*HID + c*HID, yt, m0, o);
            float bias = D_b[l*HID + c];
#pragma unroll
            for (int j = 0; j < 16; ++j) {
                int m = m0 + j;
                float g = gs[m*HID + c];
                xs[m*HID + c] += (o[j] + bias) * (1.0f - g);
            }
        }
        // a = tanh(y @ A_w.T), bt = y @ B_w.T  (N=128 combined, 4 threads/col, 8 rows each)
        {
            int c2 = tid & 127, q = tid >> 7, m0q = q * 8;
            float o[8];
            const float* w = (c2 < DSTATE)
                           ? (A_w + l*DSTATE*HID + c2*HID)
                           : (B_w + l*DSTATE*HID + (c2-DSTATE)*HID);
            gemm_col<HID,8>(w, yt, m0q, o);
            if (c2 < DSTATE) {
#pragma unroll
                for (int j = 0; j < 8; ++j) at[c2*LDT + m0q + j] = tanhf(o[j]);
            } else {
#pragma unroll
                for (int j = 0; j < 8; ++j) btt[(c2-DSTATE)*LDT + m0q + j] = o[j];
            }
        }
        __syncthreads();

        // scan: h = a*h + bt over s, in place into at (becomes hs)
        if (tid < BT*DSTATE) {
            int e = tid / DSTATE, d = tid % DSTATE;
            float h = 0.f;
#pragma unroll
            for (int s = 0; s < S_SEQ; ++s) {
                int m = e*S_SEQ + s;
                h = at[d*LDT + m] * h + btt[d*LDT + m];
                at[d*LDT + m] = h;
            }
        }
        __syncthreads();

        // ys = hs @ C_w.T ; xs += ys * g
        {
            float o[16];
            gemm_col<DSTATE,16>(C_w + l*HID*DSTATE + c*DSTATE, at, m0, o);
#pragma unroll
            for (int j = 0; j < 16; ++j) {
                int m = m0 + j;
                xs[m*HID + c] += o[j] * gs[m*HID + c];
            }
        }
        __syncthreads();

        // FFN
        layer_norm<true>(xs, yt, ng, nb, tid);
        __syncthreads();
        {   // mid = gelu(y @ w1.T + b1), one column per thread, all 32 rows
            float o[32];
            gemm_col<HID,32>(ffn_w1 + l*FF*HID + tid*HID, yt, 0, o);
            float bias = ffn_b1[l*FF + tid];
#pragma unroll
            for (int j = 0; j < 32; ++j)
                mid[tid*LDT + j] = gelu_exact(o[j] + bias);
        }
        __syncthreads();
        {   // xs += mid @ w2.T + b2
            float o[16];
            gemm_col<FF,16>(ffn_w2 + l*HID*FF + c*FF, mid, m0, o);
            float bias = ffn_b2[l*HID + c];
#pragma unroll
            for (int j = 0; j < 16; ++j) xs[(m0+j)*HID + c] += o[j] + bias;
        }
        __syncthreads();
    }

    // ---------------- head ----------------
    layer_norm<false>(xs, gs, fln_g, fln_b, tid);   // gs = final LN, row-major
    __syncthreads();

    float* scores = red;            // [BT][16] (slots 0..14 used)
    float* wts    = red + 32;       // [BT][16]
    float* ov     = red + 64;       // [BT][HID]
    float* rr     = ov + BT*HID;    // [BT][128]
    float* zz     = rr + BT*128;    // [BT][NCLS]
    float* lse    = zz + BT*NCLS;   // [BT]

    {   // attention scores: warp w handles neighbor s=w+1 for both elements
        int warp = tid >> 5, lane = tid & 31;
        if (warp < 15) {
            for (int e = 0; e < BT; ++e) {
                const float* y0 = gs + (e*S_SEQ)*HID;
                const float* ysn = gs + (e*S_SEQ + warp + 1)*HID;
                float ssum = 0.f;
                for (int i = lane; i < HID; i += 32)
                    ssum += y0[i]*attn_w[i] + ysn[i]*attn_w[HID + i];
#pragma unroll
                for (int o = 16; o >= 1; o >>= 1)
                    ssum += __shfl_xor_sync(0xffffffffu, ssum, o);
                if (lane == 0) scores[e*16 + warp] = ssum + attn_b[0];
            }
        }
    }
    __syncthreads();
    if (tid < BT) {  // softmax over 15 neighbors
        int e = tid;
        float mx = -1e30f;
        for (int s = 0; s < 15; ++s) mx = fmaxf(mx, scores[e*16 + s]);
        float sum = 0.f;
        for (int s = 0; s < 15; ++s) sum += expf(scores[e*16 + s] - mx);
        float inv = 1.0f / sum;
        for (int s = 0; s < 15; ++s) wts[e*16 + s] = expf(scores[e*16 + s] - mx) * inv;
    }
    __syncthreads();
    {   // out_vec = node + sum_s nbr[s]*w[s]
        int e = tid >> 8, h = tid & 255;
        float v = gs[(e*S_SEQ)*HID + h];
#pragma unroll
        for (int s = 1; s < S_SEQ; ++s)
            v += gs[(e*S_SEQ + s)*HID + h] * wts[e*16 + s - 1];
        ov[e*HID + h] = v;
    }
    __syncthreads();
    if (tid < BT*128) {  // fc1 + relu
        int e = tid >> 7, j = tid & 127;
        const float* w = out_w + j*HID;
        float acc = out_b[j];
        for (int h = 0; h < HID; ++h) acc += ov[e*HID + h] * w[h];
        rr[e*128 + j] = fmaxf(acc, 0.f);
    }
    __syncthreads();
    if (tid < BT*NCLS) {  // classifier
        int e = tid / NCLS, cc = tid % NCLS;
        const float* w = cls_w + cc*128;
        float acc = cls_b[cc];
        for (int j = 0; j < 128; ++j) acc += rr[e*128 + j] * w[j];
        zz[e*NCLS + cc] = acc;
    }
    __syncthreads();
    if (tid < BT) {  // logsumexp
        int e = tid;
        float mx = -1e30f;
        for (int cc = 0; cc < NCLS; ++cc) mx = fmaxf(mx, zz[e*NCLS + cc]);
        float sum = 0.f;
        for (int cc = 0; cc < NCLS; ++cc) sum += expf(zz[e*NCLS + cc] - mx);
        lse[e] = mx + logf(sum);
    }
    __syncthreads();
    if (tid < BT*NCLS) {
        int e = tid / NCLS, cc = tid % NCLS;
        out[(size_t)(b0 + e)*NCLS + cc] = zz[e*NCLS + cc] - lse[e];
    }
}

extern "C" void kernel_launch(void* const* d_in, const int* in_sizes, int n_in,
                              void* d_out, int out_size)
{
    const float* data   = (const float*)d_in[0];
    const float* in_w   = (const float*)d_in[1];
    const float* in_b   = (const float*)d_in[2];
    const float* norm_g = (const float*)d_in[3];
    const float* norm_b = (const float*)d_in[4];
    const float* A_w    = (const float*)d_in[5];
    const float* B_w    = (const float*)d_in[6];
    const float* C_w    = (const float*)d_in[7];
    const float* D_w    = (const float*)d_in[8];
    const float* D_b    = (const float*)d_in[9];
    const float* gate_w = (const float*)d_in[10];
    const float* gate_b = (const float*)d_in[11];
    const float* ffn_w1 = (const float*)d_in[12];
    const float* ffn_b1 = (const float*)d_in[13];
    const float* ffn_w2 = (const float*)d_in[14];
    const float* ffn_b2 = (const float*)d_in[15];
    const float* fln_g  = (const float*)d_in[16];
    const float* fln_b  = (const float*)d_in[17];
    const float* out_w  = (const float*)d_in[18];
    const float* out_b  = (const float*)d_in[19];
    const float* cls_w  = (const float*)d_in[20];
    const float* cls_b  = (const float*)d_in[21];
    const float* attn_w = (const float*)d_in[22];
    const float* attn_b = (const float*)d_in[23];
    float* out = (float*)d_out;

    int Btotal = in_sizes[0] / (S_SEQ * INDIM);
    int grid = Btotal / BT;

    cudaFuncSetAttribute(mamba_fused_kernel,
                         cudaFuncAttributeMaxDynamicSharedMemorySize,
                         SMEM_FLOATS * (int)sizeof(float));

    mamba_fused_kernel<<<grid, NTHREADS, SMEM_FLOATS * sizeof(float)>>>(
        data, in_w, in_b, norm_g, norm_b, A_w, B_w, C_w, D_w, D_b,
        gate_w, gate_b, ffn_w1, ffn_b1, ffn_w2, ffn_b2,
        fln_g, fln_b, out_w, out_b, cls_w, cls_b, attn_w, attn_b, out);
}

// round 3
// speedup vs baseline: 1.2118x; 1.2118x over previous
#include <cuda_runtime.h>
#include <math.h>

// ---------------- problem constants ----------------
#define S_SEQ   16
#define HID     256
#define INDIM   512
#define DSTATE  64
#define NLAYER  6
#define NCLS    40
#define FF      512
#define EPSV    1e-5f

// ---------------- kernel config --------------------
#define BT        2                 // batch elements per CTA
#define MROWS     (BT*S_SEQ)        // 32 rows
#define NTHREADS  512
#define LDT       36                // padded M-stride of transposed smem tiles
#define KB        32                // k-chunk for weight staging
#define WSP       36                // padded row stride of ws tile

// smem float offsets
#define OFF_XS   0                          // [MROWS][HID] residual, row-major
#define OFF_GS   (OFF_XS + MROWS*HID)       // [MROWS][HID] gate / final-LN
#define OFF_YT   (OFF_GS + MROWS*HID)       // [HID][LDT]  LN output (transposed)
#define OFF_MID  (OFF_YT + HID*LDT)         // [FF][LDT]   data-T / ffn mid (transposed); head scratch
#define OFF_AB   (OFF_MID + FF*LDT)         // at[DSTATE][LDT], btt[DSTATE][LDT]
#define OFF_WS   (OFF_AB + 2*DSTATE*LDT)    // [256][WSP] staged weight chunk
#define SMEM_FLOATS (OFF_WS + 256*WSP)      // 57856 floats = 231424 B (< 232448)

typedef unsigned long long ull;

__device__ __forceinline__ ull ffma2(ull a, ull b, ull c) {
    ull d;
    asm("fma.rn.f32x2 %0, %1, %2, %3;" : "=l"(d) : "l"(a), "l"(b), "l"(c));
    return d;
}
__device__ __forceinline__ ull bcast2(float x) {
    ull r;
    asm("mov.b64 %0, {%1, %1};" : "=l"(r) : "f"(x));
    return r;
}
__device__ __forceinline__ float2 unpack2(ull v) {
    float2 r;
    asm("mov.b64 {%0, %1}, %2;" : "=f"(r.x), "=f"(r.y) : "l"(v));
    return r;
}
__device__ __forceinline__ float gelu_exact(float x) {
    return 0.5f * x * (1.0f + erff(x * 0.70710678118654752f));
}

// ---- staged-weight GEMM ----------------------------------------------------
// Wg: global weights [NCOLS][K] row-major (this pass's columns only).
// inT: [K][LDT] transposed smem activations. Computes out[j] = sum_k inT[k][m0+j]*Wg[row][k].
// All 512 threads must call (cooperative loader + barriers inside).
template<int RPT>
__device__ __forceinline__ void gemm_smem(const float* __restrict__ Wg,
                                          int K, int NCOLS,
                                          const float* __restrict__ inT,
                                          int m0, int wsrow,
                                          float* __restrict__ ws,
                                          float* __restrict__ out, int tid)
{
    ull acc[RPT/2];
#pragma unroll
    for (int i = 0; i < RPT/2; ++i) acc[i] = 0ull;

    for (int k0 = 0; k0 < K; k0 += KB) {
        __syncthreads();   // previous ws consumers are done
        {   // coalesced stage: warp touches 4 lines per LDG.128 (8 lanes/row)
            int nfl4 = NCOLS * (KB/4);
            for (int i = tid; i < nfl4; i += NTHREADS) {
                int r = i >> 3, kk4 = (i & 7) << 2;
                float4 v = __ldg(reinterpret_cast<const float4*>(Wg + r*K + k0 + kk4));
                *reinterpret_cast<float4*>(ws + r*WSP + kk4) = v;
            }
        }
        __syncthreads();
        const float* wr   = ws + wsrow*WSP;
        const float* inTc = inT + k0*LDT;
#pragma unroll
        for (int kk4 = 0; kk4 < KB; kk4 += 4) {
            float4 w4 = *reinterpret_cast<const float4*>(wr + kk4);
            float wk[4] = {w4.x, w4.y, w4.z, w4.w};
#pragma unroll
            for (int kk = 0; kk < 4; ++kk) {
                ull wb = bcast2(wk[kk]);
                const ulonglong2* p =
                    reinterpret_cast<const ulonglong2*>(inTc + (kk4 + kk)*LDT + m0);
#pragma unroll
                for (int j = 0; j < RPT/4; ++j) {
                    ulonglong2 v = p[j];
                    acc[2*j]     = ffma2(v.x, wb, acc[2*j]);
                    acc[2*j + 1] = ffma2(v.y, wb, acc[2*j + 1]);
                }
            }
        }
    }
#pragma unroll
    for (int j = 0; j < RPT/2; ++j) {
        float2 f = unpack2(acc[j]);
        out[2*j] = f.x; out[2*j + 1] = f.y;
    }
}

// A/B combined variant: rows 0..63 from Aw, 64..127 from Bw (each [64][256]).
__device__ __forceinline__ void gemm_smem_ab(const float* __restrict__ Aw,
                                             const float* __restrict__ Bw,
                                             const float* __restrict__ inT,
                                             int m0, int wsrow,
                                             float* __restrict__ ws,
                                             float* __restrict__ out, int tid)
{
    ull acc[4] = {0ull, 0ull, 0ull, 0ull};
    for (int k0 = 0; k0 < HID; k0 += KB) {
        __syncthreads();
        for (int i = tid; i < 128*(KB/4); i += NTHREADS) {
            int r = i >> 3, kk4 = (i & 7) << 2;
            const float* src = (r < DSTATE) ? (Aw + r*HID) : (Bw + (r - DSTATE)*HID);
            float4 v = __ldg(reinterpret_cast<const float4*>(src + k0 + kk4));
            *reinterpret_cast<float4*>(ws + r*WSP + kk4) = v;
        }
        __syncthreads();
        const float* wr   = ws + wsrow*WSP;
        const float* inTc = inT + k0*LDT;
#pragma unroll
        for (int kk4 = 0; kk4 < KB; kk4 += 4) {
            float4 w4 = *reinterpret_cast<const float4*>(wr + kk4);
            float wk[4] = {w4.x, w4.y, w4.z, w4.w};
#pragma unroll
            for (int kk = 0; kk < 4; ++kk) {
                ull wb = bcast2(wk[kk]);
                const ulonglong2* p =
                    reinterpret_cast<const ulonglong2*>(inTc + (kk4 + kk)*LDT + m0);
                ulonglong2 v = p[0];
                acc[0] = ffma2(v.x, wb, acc[0]);
                acc[1] = ffma2(v.y, wb, acc[1]);
                ulonglong2 v2 = p[1];
                acc[2] = ffma2(v2.x, wb, acc[2]);
                acc[3] = ffma2(v2.y, wb, acc[3]);
            }
        }
    }
#pragma unroll
    for (int j = 0; j < 4; ++j) {
        float2 f = unpack2(acc[j]);
        out[2*j] = f.x; out[2*j + 1] = f.y;
    }
}

// LayerNorm of xs[MROWS][HID]. 16 lanes per row (2 rows per warp).
template<bool TRANS>
__device__ __forceinline__ void layer_norm(const float* __restrict__ xs,
                                           float* __restrict__ dst,
                                           const float* __restrict__ gw,
                                           const float* __restrict__ bw,
                                           int tid)
{
    int warp = tid >> 5, lane = tid & 31;
    int m   = warp*2 + (lane >> 4);
    int sub = lane & 15;
    const float* row = xs + m*HID + sub*16;
    float v[16];
#pragma unroll
    for (int i = 0; i < 4; ++i) {
        float4 t = *reinterpret_cast<const float4*>(row + i*4);
        v[4*i] = t.x; v[4*i+1] = t.y; v[4*i+2] = t.z; v[4*i+3] = t.w;
    }
    float s = 0.f;
#pragma unroll
    for (int i = 0; i < 16; ++i) s += v[i];
#pragma unroll
    for (int o = 8; o >= 1; o >>= 1) s += __shfl_xor_sync(0xffffffffu, s, o);
    float mean = s * (1.0f/HID);
    float q = 0.f;
#pragma unroll
    for (int i = 0; i < 16; ++i) { float d = v[i] - mean; q += d*d; }
#pragma unroll
    for (int o = 8; o >= 1; o >>= 1) q += __shfl_xor_sync(0xffffffffu, q, o);
    float rstd = rsqrtf(q * (1.0f/HID) + EPSV);
    int h0 = sub*16;
#pragma unroll
    for (int i = 0; i < 16; ++i) {
        float y = (v[i] - mean) * rstd * gw[h0+i] + bw[h0+i];
        if (TRANS) dst[(h0+i)*LDT + m] = y;
        else       dst[m*HID + h0 + i] = y;
    }
}

__global__ void __launch_bounds__(NTHREADS, 1)
mamba_fused_kernel(const float* __restrict__ data,
                   const float* __restrict__ in_w,  const float* __restrict__ in_b,
                   const float* __restrict__ norm_g,const float* __restrict__ norm_b,
                   const float* __restrict__ A_w,   const float* __restrict__ B_w,
                   const float* __restrict__ C_w,
                   const float* __restrict__ D_w,   const float* __restrict__ D_b,
                   const float* __restrict__ gate_w,const float* __restrict__ gate_b,
                   const float* __restrict__ ffn_w1,const float* __restrict__ ffn_b1,
                   const float* __restrict__ ffn_w2,const float* __restrict__ ffn_b2,
                   const float* __restrict__ fln_g, const float* __restrict__ fln_b,
                   const float* __restrict__ out_w, const float* __restrict__ out_b,
                   const float* __restrict__ cls_w, const float* __restrict__ cls_b,
                   const float* __restrict__ attn_w,const float* __restrict__ attn_b,
                   float* __restrict__ out)
{
    extern __shared__ float sm[];
    float* xs  = sm + OFF_XS;
    float* gs  = sm + OFF_GS;
    float* yt  = sm + OFF_YT;
    float* mid = sm + OFF_MID;
    float* at  = sm + OFF_AB;
    float* btt = at + DSTATE*LDT;
    float* ws  = sm + OFF_WS;

    const int tid = threadIdx.x;
    const int b0  = blockIdx.x * BT;

    // ---- load input rows [32][512] transposed into mid (as datat[k][m]) ----
    {
        const float4* gdat4 =
            reinterpret_cast<const float4*>(data + (size_t)b0 * S_SEQ * INDIM);
#pragma unroll
        for (int i = 0; i < (MROWS*INDIM/4)/NTHREADS; ++i) {
            int idx = tid + i*NTHREADS;
            float4 v = __ldg(gdat4 + idx);
            int lin = idx * 4;
            int m = lin >> 9;          // /512
            int k = lin & (INDIM-1);
            mid[(k+0)*LDT + m] = v.x;
            mid[(k+1)*LDT + m] = v.y;
            mid[(k+2)*LDT + m] = v.z;
            mid[(k+3)*LDT + m] = v.w;
        }
    }

    const int c    = tid & 255;
    const int half = tid >> 8;
    const int m0   = half * 16;

    // ---- input projection: xs = data @ in_w.T + in_b ----
    {
        float o[16];
        gemm_smem<16>(in_w, INDIM, HID, mid, m0, c, ws, o, tid);
        float bias = in_b[c];
#pragma unroll
        for (int j = 0; j < 16; ++j) xs[(m0+j)*HID + c] = o[j] + bias;
    }
    __syncthreads();

    // ---------------- 6 layers ----------------
    for (int l = 0; l < NLAYER; ++l) {
        const float* ng = norm_g + l*HID;
        const float* nb = norm_b + l*HID;

        layer_norm<true>(xs, yt, ng, nb, tid);
        // gate = sigmoid(y @ gate_w.T + gate_b)   (gemm_smem's lead barrier covers yt)
        {
            float o[16];
            gemm_smem<16>(gate_w + l*HID*HID, HID, HID, yt, m0, c, ws, o, tid);
            float bias = gate_b[l*HID + c];
#pragma unroll
            for (int j = 0; j < 16; ++j)
                gs[(m0+j)*HID + c] = 1.0f / (1.0f + expf(-(o[j] + bias)));
        }
        // dt = y @ D_w.T + D_b ; xs += dt * (1 - g)
        {
            float o[16];
            gemm_smem<16>(D_w + l*HID*HID, HID, HID, yt, m0, c, ws, o, tid);
            float bias = D_b[l*HID + c];
#pragma unroll
            for (int j = 0; j < 16; ++j) {
                int m = m0 + j;
                float g = gs[m*HID + c];
                xs[m*HID + c] += (o[j] + bias) * (1.0f - g);
            }
        }
        // a = tanh(y @ A_w.T), bt = y @ B_w.T  (N=128 combined, 4 threads/col, 8 rows)
        {
            int c2 = tid & 127, q = tid >> 7, m0q = q * 8;
            float o[8];
            gemm_smem_ab(A_w + l*DSTATE*HID, B_w + l*DSTATE*HID,
                         yt, m0q, c2, ws, o, tid);
            if (c2 < DSTATE) {
#pragma unroll
                for (int j = 0; j < 8; ++j) at[c2*LDT + m0q + j] = tanhf(o[j]);
            } else {
#pragma unroll
                for (int j = 0; j < 8; ++j) btt[(c2-DSTATE)*LDT + m0q + j] = o[j];
            }
        }
        __syncthreads();

        // scan: h = a*h + bt over s, in place into at (becomes hs)
        if (tid < BT*DSTATE) {
            int e = tid / DSTATE, d = tid % DSTATE;
            float h = 0.f;
#pragma unroll
            for (int s = 0; s < S_SEQ; ++s) {
                int m = e*S_SEQ + s;
                h = at[d*LDT + m] * h + btt[d*LDT + m];
                at[d*LDT + m] = h;
            }
        }
        __syncthreads();

        // ys = hs @ C_w.T ; xs += ys * g
        {
            float o[16];
            gemm_smem<16>(C_w + l*HID*DSTATE, DSTATE, HID, at, m0, c, ws, o, tid);
#pragma unroll
            for (int j = 0; j < 16; ++j) {
                int m = m0 + j;
                xs[m*HID + c] += o[j] * gs[m*HID + c];
            }
        }
        __syncthreads();

        // FFN
        layer_norm<true>(xs, yt, ng, nb, tid);
        // mid = gelu(y @ w1.T + b1), two 256-column passes
#pragma unroll
        for (int pass = 0; pass < 2; ++pass) {
            float o[16];
            gemm_smem<16>(ffn_w1 + l*FF*HID + pass*256*HID, HID, HID, yt, m0, c, ws, o, tid);
            float bias = ffn_b1[l*FF + pass*256 + c];
#pragma unroll
            for (int j = 0; j < 16; ++j)
                mid[(pass*256 + c)*LDT + m0 + j] = gelu_exact(o[j] + bias);
        }
        // xs += mid @ w2.T + b2   (gemm_smem's lead barrier covers mid)
        {
            float o[16];
            gemm_smem<16>(ffn_w2 + l*HID*FF, FF, HID, mid, m0, c, ws, o, tid);
            float bias = ffn_b2[l*HID + c];
#pragma unroll
            for (int j = 0; j < 16; ++j) xs[(m0+j)*HID + c] += o[j] + bias;
        }
        __syncthreads();
    }

    // ---------------- head ----------------
    layer_norm<false>(xs, gs, fln_g, fln_b, tid);   // gs = final LN, row-major
    __syncthreads();

    float* red    = mid;            // reuse mid as head scratch
    float* scores = red;            // [BT][16] (slots 0..14 used)
    float* wts    = red + 32;       // [BT][16]
    float* ov     = red + 64;       // [BT][HID]
    float* rr     = ov + BT*HID;    // [BT][128]
    float* zz     = rr + BT*128;    // [BT][NCLS]
    float* lse    = zz + BT*NCLS;   // [BT]

    {   // attention scores: warp w handles neighbor s=w+1 for both elements
        int warp = tid >> 5, lane = tid & 31;
        if (warp < 15) {
            for (int e = 0; e < BT; ++e) {
                const float* y0 = gs + (e*S_SEQ)*HID;
                const float* ysn = gs + (e*S_SEQ + warp + 1)*HID;
                float ssum = 0.f;
                for (int i = lane; i < HID; i += 32)
                    ssum += y0[i]*attn_w[i] + ysn[i]*attn_w[HID + i];
#pragma unroll
                for (int o = 16; o >= 1; o >>= 1)
                    ssum += __shfl_xor_sync(0xffffffffu, ssum, o);
                if (lane == 0) scores[e*16 + warp] = ssum + attn_b[0];
            }
        }
    }
    __syncthreads();
    if (tid < BT) {  // softmax over 15 neighbors
        int e = tid;
        float mx = -1e30f;
        for (int s = 0; s < 15; ++s) mx = fmaxf(mx, scores[e*16 + s]);
        float sum = 0.f;
        for (int s = 0; s < 15; ++s) sum += expf(scores[e*16 + s] - mx);
        float inv = 1.0f / sum;
        for (int s = 0; s < 15; ++s) wts[e*16 + s] = expf(scores[e*16 + s] - mx) * inv;
    }
    __syncthreads();
    {   // out_vec = node + sum_s nbr[s]*w[s]
        int e = tid >> 8, h = tid & 255;
        float v = gs[(e*S_SEQ)*HID + h];
#pragma unroll
        for (int s = 1; s < S_SEQ; ++s)
            v += gs[(e*S_SEQ + s)*HID + h] * wts[e*16 + s - 1];
        ov[e*HID + h] = v;
    }
    __syncthreads();
    if (tid < BT*128) {  // fc1 + relu
        int e = tid >> 7, j = tid & 127;
        const float* w = out_w + j*HID;
        float acc = out_b[j];
        for (int h = 0; h < HID; ++h) acc += ov[e*HID + h] * w[h];
        rr[e*128 + j] = fmaxf(acc, 0.f);
    }
    __syncthreads();
    if (tid < BT*NCLS) {  // classifier
        int e = tid / NCLS, cc = tid % NCLS;
        const float* w = cls_w + cc*128;
        float acc = cls_b[cc];
        for (int j = 0; j < 128; ++j) acc += rr[e*128 + j] * w[j];
        zz[e*NCLS + cc] = acc;
    }
    __syncthreads();
    if (tid < BT) {  // logsumexp
        int e = tid;
        float mx = -1e30f;
        for (int cc = 0; cc < NCLS; ++cc) mx = fmaxf(mx, zz[e*NCLS + cc]);
        float sum = 0.f;
        for (int cc = 0; cc < NCLS; ++cc) sum += expf(zz[e*NCLS + cc] - mx);
        lse[e] = mx + logf(sum);
    }
    __syncthreads();
    if (tid < BT*NCLS) {
        int e = tid / NCLS, cc = tid % NCLS;
        out[(size_t)(b0 + e)*NCLS + cc] = zz[e*NCLS + cc] - lse[e];
    }
}

extern "C" void kernel_launch(void* const* d_in, const int* in_sizes, int n_in,
                              void* d_out, int out_size)
{
    const float* data   = (const float*)d_in[0];
    const float* in_w   = (const float*)d_in[1];
    const float* in_b   = (const float*)d_in[2];
    const float* norm_g = (const float*)d_in[3];
    const float* norm_b = (const float*)d_in[4];
    const float* A_w    = (const float*)d_in[5];
    const float* B_w    = (const float*)d_in[6];
    const float* C_w    = (const float*)d_in[7];
    const float* D_w    = (const float*)d_in[8];
    const float* D_b    = (const float*)d_in[9];
    const float* gate_w = (const float*)d_in[10];
    const float* gate_b = (const float*)d_in[11];
    const float* ffn_w1 = (const float*)d_in[12];
    const float* ffn_b1 = (const float*)d_in[13];
    const float* ffn_w2 = (const float*)d_in[14];
    const float* ffn_b2 = (const float*)d_in[15];
    const float* fln_g  = (const float*)d_in[16];
    const float* fln_b  = (const float*)d_in[17];
    const float* out_w  = (const float*)d_in[18];
    const float* out_b  = (const float*)d_in[19];
    const float* cls_w  = (const float*)d_in[20];
    const float* cls_b  = (const float*)d_in[21];
    const float* attn_w = (const float*)d_in[22];
    const float* attn_b = (const float*)d_in[23];
    float* out = (float*)d_out;

    int Btotal = in_sizes[0] / (S_SEQ * INDIM);
    int grid = Btotal / BT;

    cudaFuncSetAttribute(mamba_fused_kernel,
                         cudaFuncAttributeMaxDynamicSharedMemorySize,
                         SMEM_FLOATS * (int)sizeof(float));

    mamba_fused_kernel<<<grid, NTHREADS, SMEM_FLOATS * sizeof(float)>>>(
        data, in_w, in_b, norm_g, norm_b, A_w, B_w, C_w, D_w, D_b,
        gate_w, gate_b, ffn_w1, ffn_b1, ffn_w2, ffn_b2,
        fln_g, fln_b, out_w, out_b, cls_w, cls_b, attn_w, attn_b, out);
}

// round 5
// speedup vs baseline: 1.4830x; 1.2239x over previous
#include <cuda_runtime.h>
#include <math.h>

// ---------------- problem constants ----------------
#define S_SEQ   16
#define HID     256
#define INDIM   512
#define DSTATE  64
#define NLAYER  6
#define NCLS    40
#define FF      512
#define EPSV    1e-5f

// ---------------- kernel config --------------------
#define BT        2                 // batch elements per CTA
#define MROWS     (BT*S_SEQ)        // 32 rows
#define NTHREADS  512
#define LDT       36                // padded M-stride of transposed smem tiles
#define KB        32                // k-chunk for weight staging
#define WSP       36                // padded row stride of ws tile

// smem float offsets
#define OFF_XS   0                          // [MROWS][HID] residual, row-major
#define OFF_GS   (OFF_XS + MROWS*HID)       // [MROWS][HID] gate / final-LN
#define OFF_YT   (OFF_GS + MROWS*HID)       // [HID][LDT]  LN output (transposed)
#define OFF_MID  (OFF_YT + HID*LDT)         // [FF][LDT]   data-T / ffn mid (transposed); head scratch
#define OFF_AB   (OFF_MID + FF*LDT)         // at[DSTATE][LDT], btt[DSTATE][LDT]
#define OFF_WS   (OFF_AB + 2*DSTATE*LDT)    // [256][WSP] staged weight chunk
#define SMEM_FLOATS (OFF_WS + 256*WSP)      // 231424 B

typedef unsigned long long ull;

__device__ __forceinline__ ull ffma2(ull a, ull b, ull c) {
    ull d;
    asm("fma.rn.f32x2 %0, %1, %2, %3;" : "=l"(d) : "l"(a), "l"(b), "l"(c));
    return d;
}
__device__ __forceinline__ ull bcast2(float x) {
    ull r;
    asm("mov.b64 %0, {%1, %1};" : "=l"(r) : "f"(x));
    return r;
}
__device__ __forceinline__ float2 unpack2(ull v) {
    float2 r;
    asm("mov.b64 {%0, %1}, %2;" : "=f"(r.x), "=f"(r.y) : "l"(v));
    return r;
}
__device__ __forceinline__ float gelu_exact(float x) {
    return 0.5f * x * (1.0f + erff(x * 0.70710678118654752f));
}

// ---- staged-weight GEMM, 2 columns x RPT rows per thread -------------------
// Columns c0, c0+1; rows m0..m0+RPT-1. inT: [K][LDT] transposed activations.
// Weight chunk staged to ws[col][WSP] cooperatively, with register prefetch of
// the next chunk issued right after the publish barrier (hides LDG latency).
// out[0..RPT) = col c0 results, out[RPT..2*RPT) = col c0+1 results.
// All 512 threads must call (barriers inside).
template<int NCOLS, int RPT, bool SPLIT>
__device__ __forceinline__ void gemm2(const float* __restrict__ WgA,
                                      const float* __restrict__ WgB,
                                      int K,
                                      const float* __restrict__ inT,
                                      int m0, int c0,
                                      float* __restrict__ ws,
                                      float* __restrict__ out, int tid)
{
    constexpr int PF = NCOLS / 64;     // float4 staged per thread per chunk
    ull acc0[RPT/2], acc1[RPT/2];
#pragma unroll
    for (int i = 0; i < RPT/2; ++i) { acc0[i] = 0ull; acc1[i] = 0ull; }

    float4 pf[PF];
#pragma unroll
    for (int t = 0; t < PF; ++t) {
        int i = tid + t*NTHREADS;
        int r = i >> 3, kk4 = (i & 7) << 2;
        const float* src = SPLIT
            ? ((r < NCOLS/2) ? (WgA + r*K) : (WgB + (r - NCOLS/2)*K))
            : (WgA + r*K);
        pf[t] = __ldg(reinterpret_cast<const float4*>(src + kk4));
    }

    for (int k0 = 0; k0 < K; k0 += KB) {
        __syncthreads();   // previous ws consumers done / inT producers done
#pragma unroll
        for (int t = 0; t < PF; ++t) {
            int i = tid + t*NTHREADS;
            int r = i >> 3, kk4 = (i & 7) << 2;
            *reinterpret_cast<float4*>(ws + r*WSP + kk4) = pf[t];
        }
        __syncthreads();
        if (k0 + KB < K) {   // prefetch next chunk; overlaps with compute below
#pragma unroll
            for (int t = 0; t < PF; ++t) {
                int i = tid + t*NTHREADS;
                int r = i >> 3, kk4 = (i & 7) << 2;
                const float* src = SPLIT
                    ? ((r < NCOLS/2) ? (WgA + r*K) : (WgB + (r - NCOLS/2)*K))
                    : (WgA + r*K);
                pf[t] = __ldg(reinterpret_cast<const float4*>(src + k0 + KB + kk4));
            }
        }
        const float* w0  = ws + c0*WSP;
        const float* w1  = w0 + WSP;
        const float* inb = inT + k0*LDT + m0;
#pragma unroll
        for (int kk4 = 0; kk4 < KB; kk4 += 4) {
            float4 wa = *reinterpret_cast<const float4*>(w0 + kk4);
            float4 wb = *reinterpret_cast<const float4*>(w1 + kk4);
            float wav[4] = {wa.x, wa.y, wa.z, wa.w};
            float wbv[4] = {wb.x, wb.y, wb.z, wb.w};
#pragma unroll
            for (int kk = 0; kk < 4; ++kk) {
                ull ba = bcast2(wav[kk]);
                ull bb = bcast2(wbv[kk]);
                const ulonglong2* p =
                    reinterpret_cast<const ulonglong2*>(inb + (kk4 + kk)*LDT);
#pragma unroll
                for (int j = 0; j < RPT/4; ++j) {
                    ulonglong2 v = p[j];
                    acc0[2*j]   = ffma2(v.x, ba, acc0[2*j]);
                    acc0[2*j+1] = ffma2(v.y, ba, acc0[2*j+1]);
                    acc1[2*j]   = ffma2(v.x, bb, acc1[2*j]);
                    acc1[2*j+1] = ffma2(v.y, bb, acc1[2*j+1]);
                }
            }
        }
    }
#pragma unroll
    for (int j = 0; j < RPT/2; ++j) {
        float2 f0 = unpack2(acc0[j]);
        out[2*j] = f0.x; out[2*j+1] = f0.y;
        float2 f1 = unpack2(acc1[j]);
        out[RPT + 2*j] = f1.x; out[RPT + 2*j+1] = f1.y;
    }
}

// LayerNorm of xs[MROWS][HID]. 16 lanes per row (2 rows per warp).
template<bool TRANS>
__device__ __forceinline__ void layer_norm(const float* __restrict__ xs,
                                           float* __restrict__ dst,
                                           const float* __restrict__ gw,
                                           const float* __restrict__ bw,
                                           int tid)
{
    int warp = tid >> 5, lane = tid & 31;
    int m   = warp*2 + (lane >> 4);
    int sub = lane & 15;
    const float* row = xs + m*HID + sub*16;
    float v[16];
#pragma unroll
    for (int i = 0; i < 4; ++i) {
        float4 t = *reinterpret_cast<const float4*>(row + i*4);
        v[4*i] = t.x; v[4*i+1] = t.y; v[4*i+2] = t.z; v[4*i+3] = t.w;
    }
    float s = 0.f;
#pragma unroll
    for (int i = 0; i < 16; ++i) s += v[i];
#pragma unroll
    for (int o = 8; o >= 1; o >>= 1) s += __shfl_xor_sync(0xffffffffu, s, o);
    float mean = s * (1.0f/HID);
    float q = 0.f;
#pragma unroll
    for (int i = 0; i < 16; ++i) { float d = v[i] - mean; q += d*d; }
#pragma unroll
    for (int o = 8; o >= 1; o >>= 1) q += __shfl_xor_sync(0xffffffffu, q, o);
    float rstd = rsqrtf(q * (1.0f/HID) + EPSV);
    int h0 = sub*16;
#pragma unroll
    for (int i = 0; i < 16; ++i) {
        float y = (v[i] - mean) * rstd * gw[h0+i] + bw[h0+i];
        if (TRANS) dst[(h0+i)*LDT + m] = y;
        else       dst[m*HID + h0 + i] = y;
    }
}

__global__ void __launch_bounds__(NTHREADS, 1)
mamba_fused_kernel(const float* __restrict__ data,
                   const float* __restrict__ in_w,  const float* __restrict__ in_b,
                   const float* __restrict__ norm_g,const float* __restrict__ norm_b,
                   const float* __restrict__ A_w,   const float* __restrict__ B_w,
                   const float* __restrict__ C_w,
                   const float* __restrict__ D_w,   const float* __restrict__ D_b,
                   const float* __restrict__ gate_w,const float* __restrict__ gate_b,
                   const float* __restrict__ ffn_w1,const float* __restrict__ ffn_b1,
                   const float* __restrict__ ffn_w2,const float* __restrict__ ffn_b2,
                   const float* __restrict__ fln_g, const float* __restrict__ fln_b,
                   const float* __restrict__ out_w, const float* __restrict__ out_b,
                   const float* __restrict__ cls_w, const float* __restrict__ cls_b,
                   const float* __restrict__ attn_w,const float* __restrict__ attn_b,
                   float* __restrict__ out)
{
    extern __shared__ float sm[];
    float* xs  = sm + OFF_XS;
    float* gs  = sm + OFF_GS;
    float* yt  = sm + OFF_YT;
    float* mid = sm + OFF_MID;
    float* at  = sm + OFF_AB;
    float* btt = at + DSTATE*LDT;
    float* ws  = sm + OFF_WS;

    const int tid = threadIdx.x;
    const int b0  = blockIdx.x * BT;

    // ---- load input rows [32][512] transposed into mid (as datat[k][m]) ----
    {
        const float4* gdat4 =
            reinterpret_cast<const float4*>(data + (size_t)b0 * S_SEQ * INDIM);
#pragma unroll
        for (int i = 0; i < (MROWS*INDIM/4)/NTHREADS; ++i) {
            int idx = tid + i*NTHREADS;
            float4 v = __ldg(gdat4 + idx);
            int lin = idx * 4;
            int m = lin >> 9;          // /512
            int k = lin & (INDIM-1);
            mid[(k+0)*LDT + m] = v.x;
            mid[(k+1)*LDT + m] = v.y;
            mid[(k+2)*LDT + m] = v.z;
            mid[(k+3)*LDT + m] = v.w;
        }
    }

    // standard mapping: 2 cols x 8 rows per thread
    const int c0 = 2 * (tid & 127);
    const int m0 = (tid >> 7) * 8;
    // A/B mapping: 2 cols x 4 rows per thread
    const int c0ab = 2 * (tid & 63);
    const int m0ab = (tid >> 6) * 4;

    // ---- input projection: xs = data @ in_w.T + in_b ----
    {
        float o[16];
        gemm2<HID, 8, false>(in_w, nullptr, INDIM, mid, m0, c0, ws, o, tid);
        float2 bias = *reinterpret_cast<const float2*>(in_b + c0);
#pragma unroll
        for (int j = 0; j < 8; ++j) {
            float2 v; v.x = o[j] + bias.x; v.y = o[8+j] + bias.y;
            *reinterpret_cast<float2*>(xs + (m0+j)*HID + c0) = v;
        }
    }
    __syncthreads();

    // ---------------- 6 layers ----------------
    for (int l = 0; l < NLAYER; ++l) {
        const float* ng = norm_g + l*HID;
        const float* nb = norm_b + l*HID;

        layer_norm<true>(xs, yt, ng, nb, tid);
        // gate = sigmoid(y @ gate_w.T + gate_b)   (gemm2 lead barrier covers yt)
        {
            float o[16];
            gemm2<HID, 8, false>(gate_w + l*HID*HID, nullptr, HID, yt, m0, c0, ws, o, tid);
            float2 bias = *reinterpret_cast<const float2*>(gate_b + l*HID + c0);
#pragma unroll
            for (int j = 0; j < 8; ++j) {
                float2 v;
                v.x = 1.0f / (1.0f + expf(-(o[j]   + bias.x)));
                v.y = 1.0f / (1.0f + expf(-(o[8+j] + bias.y)));
                *reinterpret_cast<float2*>(gs + (m0+j)*HID + c0) = v;
            }
        }
        // dt = y @ D_w.T + D_b ; xs += dt * (1 - g)  (same-thread gs, no sync)
        {
            float o[16];
            gemm2<HID, 8, false>(D_w + l*HID*HID, nullptr, HID, yt, m0, c0, ws, o, tid);
            float2 bias = *reinterpret_cast<const float2*>(D_b + l*HID + c0);
#pragma unroll
            for (int j = 0; j < 8; ++j) {
                int m = m0 + j;
                float2 g = *reinterpret_cast<const float2*>(gs + m*HID + c0);
                float2 x = *reinterpret_cast<const float2*>(xs + m*HID + c0);
                x.x += (o[j]   + bias.x) * (1.0f - g.x);
                x.y += (o[8+j] + bias.y) * (1.0f - g.y);
                *reinterpret_cast<float2*>(xs + m*HID + c0) = x;
            }
        }
        // a = tanh(y @ A_w.T), bt = y @ B_w.T  (128 combined cols, 2x4 per thread)
        {
            float o[8];
            gemm2<2*DSTATE, 4, true>(A_w + l*DSTATE*HID, B_w + l*DSTATE*HID,
                                     HID, yt, m0ab, c0ab, ws, o, tid);
            if (c0ab < DSTATE) {
                float4 v0, v1;
                v0.x = tanhf(o[0]); v0.y = tanhf(o[1]); v0.z = tanhf(o[2]); v0.w = tanhf(o[3]);
                v1.x = tanhf(o[4]); v1.y = tanhf(o[5]); v1.z = tanhf(o[6]); v1.w = tanhf(o[7]);
                *reinterpret_cast<float4*>(at + c0ab*LDT + m0ab)       = v0;
                *reinterpret_cast<float4*>(at + (c0ab+1)*LDT + m0ab)   = v1;
            } else {
                int d = c0ab - DSTATE;
                *reinterpret_cast<float4*>(btt + d*LDT + m0ab)     = make_float4(o[0],o[1],o[2],o[3]);
                *reinterpret_cast<float4*>(btt + (d+1)*LDT + m0ab) = make_float4(o[4],o[5],o[6],o[7]);
            }
        }
        __syncthreads();

        // scan: h = a*h + bt over s, in place into at (becomes hs)
        if (tid < BT*DSTATE) {
            int e = tid / DSTATE, d = tid % DSTATE;
            float h = 0.f;
#pragma unroll
            for (int s = 0; s < S_SEQ; ++s) {
                int m = e*S_SEQ + s;
                h = at[d*LDT + m] * h + btt[d*LDT + m];
                at[d*LDT + m] = h;
            }
        }
        __syncthreads();

        // ys = hs @ C_w.T ; xs += ys * g
        {
            float o[16];
            gemm2<HID, 8, false>(C_w + l*HID*DSTATE, nullptr, DSTATE, at, m0, c0, ws, o, tid);
#pragma unroll
            for (int j = 0; j < 8; ++j) {
                int m = m0 + j;
                float2 g = *reinterpret_cast<const float2*>(gs + m*HID + c0);
                float2 x = *reinterpret_cast<const float2*>(xs + m*HID + c0);
                x.x += o[j]   * g.x;
                x.y += o[8+j] * g.y;
                *reinterpret_cast<float2*>(xs + m*HID + c0) = x;
            }
        }
        __syncthreads();

        // FFN
        layer_norm<true>(xs, yt, ng, nb, tid);
        // mid = gelu(y @ w1.T + b1), two 256-column passes
#pragma unroll
        for (int pass = 0; pass < 2; ++pass) {
            float o[16];
            gemm2<HID, 8, false>(ffn_w1 + l*FF*HID + pass*256*HID, nullptr, HID,
                                 yt, m0, c0, ws, o, tid);
            float2 bias = *reinterpret_cast<const float2*>(ffn_b1 + l*FF + pass*256 + c0);
            float4 u0, u1;
            u0.x = gelu_exact(o[0] + bias.x); u0.y = gelu_exact(o[1] + bias.x);
            u0.z = gelu_exact(o[2] + bias.x); u0.w = gelu_exact(o[3] + bias.x);
            u1.x = gelu_exact(o[4] + bias.x); u1.y = gelu_exact(o[5] + bias.x);
            u1.z = gelu_exact(o[6] + bias.x); u1.w = gelu_exact(o[7] + bias.x);
            float* dst0 = mid + (pass*256 + c0)*LDT + m0;
            *reinterpret_cast<float4*>(dst0)     = u0;
            *reinterpret_cast<float4*>(dst0 + 4) = u1;
            float4 w0, w1;
            w0.x = gelu_exact(o[8]  + bias.y); w0.y = gelu_exact(o[9]  + bias.y);
            w0.z = gelu_exact(o[10] + bias.y); w0.w = gelu_exact(o[11] + bias.y);
            w1.x = gelu_exact(o[12] + bias.y); w1.y = gelu_exact(o[13] + bias.y);
            w1.z = gelu_exact(o[14] + bias.y); w1.w = gelu_exact(o[15] + bias.y);
            float* dst1 = mid + (pass*256 + c0 + 1)*LDT + m0;
            *reinterpret_cast<float4*>(dst1)     = w0;
            *reinterpret_cast<float4*>(dst1 + 4) = w1;
        }
        // xs += mid @ w2.T + b2   (gemm2 lead barrier covers mid)
        {
            float o[16];
            gemm2<HID, 8, false>(ffn_w2 + l*HID*FF, nullptr, FF, mid, m0, c0, ws, o, tid);
            float2 bias = *reinterpret_cast<const float2*>(ffn_b2 + l*HID + c0);
#pragma unroll
            for (int j = 0; j < 8; ++j) {
                int m = m0 + j;
                float2 x = *reinterpret_cast<const float2*>(xs + m*HID + c0);
                x.x += o[j]   + bias.x;
                x.y += o[8+j] + bias.y;
                *reinterpret_cast<float2*>(xs + m*HID + c0) = x;
            }
        }
        __syncthreads();
    }

    // ---------------- head ----------------
    layer_norm<false>(xs, gs, fln_g, fln_b, tid);   // gs = final LN, row-major
    __syncthreads();

    float* red    = mid;            // reuse mid as head scratch
    float* scores = red;            // [BT][16] (slots 0..14 used)
    float* wts    = red + 32;       // [BT][16]
    float* ov     = red + 64;       // [BT][HID]
    float* rr     = ov + BT*HID;    // [BT][128]
    float* zz     = rr + BT*128;    // [BT][NCLS]
    float* lse    = zz + BT*NCLS;   // [BT]

    {   // attention scores: warp w handles neighbor s=w+1 for both elements
        int warp = tid >> 5, lane = tid & 31;
        if (warp < 15) {
            for (int e = 0; e < BT; ++e) {
                const float* y0 = gs + (e*S_SEQ)*HID;
                const float* ysn = gs + (e*S_SEQ + warp + 1)*HID;
                float ssum = 0.f;
                for (int i = lane; i < HID; i += 32)
                    ssum += y0[i]*attn_w[i] + ysn[i]*attn_w[HID + i];
#pragma unroll
                for (int o = 16; o >= 1; o >>= 1)
                    ssum += __shfl_xor_sync(0xffffffffu, ssum, o);
                if (lane == 0) scores[e*16 + warp] = ssum + attn_b[0];
            }
        }
    }
    __syncthreads();
    if (tid < BT) {  // softmax over 15 neighbors
        int e = tid;
        float mx = -1e30f;
        for (int s = 0; s < 15; ++s) mx = fmaxf(mx, scores[e*16 + s]);
        float sum = 0.f;
        for (int s = 0; s < 15; ++s) sum += expf(scores[e*16 + s] - mx);
        float inv = 1.0f / sum;
        for (int s = 0; s < 15; ++s) wts[e*16 + s] = expf(scores[e*16 + s] - mx) * inv;
    }
    __syncthreads();
    {   // out_vec = node + sum_s nbr[s]*w[s]
        int e = tid >> 8, h = tid & 255;
        float v = gs[(e*S_SEQ)*HID + h];
#pragma unroll
        for (int s = 1; s < S_SEQ; ++s)
            v += gs[(e*S_SEQ + s)*HID + h] * wts[e*16 + s - 1];
        ov[e*HID + h] = v;
    }
    __syncthreads();
    if (tid < BT*128) {  // fc1 + relu
        int e = tid >> 7, j = tid & 127;
        const float* w = out_w + j*HID;
        float acc = out_b[j];
        for (int h = 0; h < HID; ++h) acc += ov[e*HID + h] * w[h];
        rr[e*128 + j] = fmaxf(acc, 0.f);
    }
    __syncthreads();
    if (tid < BT*NCLS) {  // classifier
        int e = tid / NCLS, cc = tid % NCLS;
        const float* w = cls_w + cc*128;
        float acc = cls_b[cc];
        for (int j = 0; j < 128; ++j) acc += rr[e*128 + j] * w[j];
        zz[e*NCLS + cc] = acc;
    }
    __syncthreads();
    if (tid < BT) {  // logsumexp
        int e = tid;
        float mx = -1e30f;
        for (int cc = 0; cc < NCLS; ++cc) mx = fmaxf(mx, zz[e*NCLS + cc]);
        float sum = 0.f;
        for (int cc = 0; cc < NCLS; ++cc) sum += expf(zz[e*NCLS + cc] - mx);
        lse[e] = mx + logf(sum);
    }
    __syncthreads();
    if (tid < BT*NCLS) {
        int e = tid / NCLS, cc = tid % NCLS;
        out[(size_t)(b0 + e)*NCLS + cc] = zz[e*NCLS + cc] - lse[e];
    }
}

extern "C" void kernel_launch(void* const* d_in, const int* in_sizes, int n_in,
                              void* d_out, int out_size)
{
    const float* data   = (const float*)d_in[0];
    const float* in_w   = (const float*)d_in[1];
    const float* in_b   = (const float*)d_in[2];
    const float* norm_g = (const float*)d_in[3];
    const float* norm_b = (const float*)d_in[4];
    const float* A_w    = (const float*)d_in[5];
    const float* B_w    = (const float*)d_in[6];
    const float* C_w    = (const float*)d_in[7];
    const float* D_w    = (const float*)d_in[8];
    const float* D_b    = (const float*)d_in[9];
    const float* gate_w = (const float*)d_in[10];
    const float* gate_b = (const float*)d_in[11];
    const float* ffn_w1 = (const float*)d_in[12];
    const float* ffn_b1 = (const float*)d_in[13];
    const float* ffn_w2 = (const float*)d_in[14];
    const float* ffn_b2 = (const float*)d_in[15];
    const float* fln_g  = (const float*)d_in[16];
    const float* fln_b  = (const float*)d_in[17];
    const float* out_w  = (const float*)d_in[18];
    const float* out_b  = (const float*)d_in[19];
    const float* cls_w  = (const float*)d_in[20];
    const float* cls_b  = (const float*)d_in[21];
    const float* attn_w = (const float*)d_in[22];
    const float* attn_b = (const float*)d_in[23];
    float* out = (float*)d_out;

    int Btotal = in_sizes[0] / (S_SEQ * INDIM);
    int grid = Btotal / BT;

    cudaFuncSetAttribute(mamba_fused_kernel,
                         cudaFuncAttributeMaxDynamicSharedMemorySize,
                         SMEM_FLOATS * (int)sizeof(float));

    mamba_fused_kernel<<<grid, NTHREADS, SMEM_FLOATS * sizeof(float)>>>(
        data, in_w, in_b, norm_g, norm_b, A_w, B_w, C_w, D_w, D_b,
        gate_w, gate_b, ffn_w1, ffn_b1, ffn_w2, ffn_b2,
        fln_g, fln_b, out_w, out_b, cls_w, cls_b, attn_w, attn_b, out);
}

// round 7
// speedup vs baseline: 1.4843x; 1.0009x over previous
#include <cuda_runtime.h>
#include <math.h>

// ---------------- problem constants ----------------
#define S_SEQ   16
#define HID     256
#define INDIM   512
#define DSTATE  64
#define NLAYER  6
#define NCLS    40
#define FF      512
#define EPSV    1e-5f

// ---------------- kernel config --------------------
#define BT        2                 // batch elements per CTA
#define MROWS     (BT*S_SEQ)        // 32 rows
#define NTHREADS  512
#define LDT       36                // padded M-stride of transposed smem tiles
#define KB        32                // k-chunk for weight staging
#define WSP       36                // padded row stride of ws tile

// smem float offsets
#define OFF_XS   0                          // [MROWS][HID] residual, row-major
#define OFF_GS   (OFF_XS + MROWS*HID)       // [MROWS][HID] gate / final-LN
#define OFF_YT   (OFF_GS + MROWS*HID)       // [HID][LDT]  LN output (transposed)
#define OFF_MID  (OFF_YT + HID*LDT)         // [FF][LDT]   data-T / ffn mid (transposed); head scratch
#define OFF_AB   (OFF_MID + FF*LDT)         // at[DSTATE][LDT], btt[DSTATE][LDT]
#define OFF_WS   (OFF_AB + 2*DSTATE*LDT)    // [256][WSP] staged weight chunk
#define SMEM_FLOATS (OFF_WS + 256*WSP)      // 231424 B

typedef unsigned long long ull;

__device__ __forceinline__ ull ffma2(ull a, ull b, ull c) {
    ull d;
    asm("fma.rn.f32x2 %0, %1, %2, %3;" : "=l"(d) : "l"(a), "l"(b), "l"(c));
    return d;
}
__device__ __forceinline__ ull bcast2(float x) {
    ull r;
    asm("mov.b64 %0, {%1, %1};" : "=l"(r) : "f"(x));
    return r;
}
__device__ __forceinline__ float2 unpack2(ull v) {
    float2 r;
    asm("mov.b64 {%0, %1}, %2;" : "=f"(r.x), "=f"(r.y) : "l"(v));
    return r;
}
__device__ __forceinline__ float gelu_exact(float x) {
    return 0.5f * x * (1.0f + erff(x * 0.70710678118654752f));
}

// ---- staged-weight GEMM, 2 columns x RPT rows per thread -------------------
// Columns c0, c0+1; rows m0..m0+RPT-1. inT: [K][LDT] transposed activations.
// Weight chunk staged to ws[col][WSP] cooperatively, with register prefetch of
// the next chunk issued right after the publish barrier (hides LDG latency).
// out[0..RPT) = col c0 results, out[RPT..2*RPT) = col c0+1 results.
// All 512 threads must call (barriers inside).
template<int NCOLS, int RPT, bool SPLIT>
__device__ __forceinline__ void gemm2(const float* __restrict__ WgA,
                                      const float* __restrict__ WgB,
                                      int K,
                                      const float* __restrict__ inT,
                                      int m0, int c0,
                                      float* __restrict__ ws,
                                      float* __restrict__ out, int tid)
{
    constexpr int PF = NCOLS / 64;     // float4 staged per thread per chunk
    ull acc0[RPT/2], acc1[RPT/2];
#pragma unroll
    for (int i = 0; i < RPT/2; ++i) { acc0[i] = 0ull; acc1[i] = 0ull; }

    float4 pf[PF];
#pragma unroll
    for (int t = 0; t < PF; ++t) {
        int i = tid + t*NTHREADS;
        int r = i >> 3, kk4 = (i & 7) << 2;
        const float* src = SPLIT
            ? ((r < NCOLS/2) ? (WgA + r*K) : (WgB + (r - NCOLS/2)*K))
            : (WgA + r*K);
        pf[t] = __ldg(reinterpret_cast<const float4*>(src + kk4));
    }

    for (int k0 = 0; k0 < K; k0 += KB) {
        __syncthreads();   // previous ws consumers done / inT producers done
#pragma unroll
        for (int t = 0; t < PF; ++t) {
            int i = tid + t*NTHREADS;
            int r = i >> 3, kk4 = (i & 7) << 2;
            *reinterpret_cast<float4*>(ws + r*WSP + kk4) = pf[t];
        }
        __syncthreads();
        if (k0 + KB < K) {   // prefetch next chunk; overlaps with compute below
#pragma unroll
            for (int t = 0; t < PF; ++t) {
                int i = tid + t*NTHREADS;
                int r = i >> 3, kk4 = (i & 7) << 2;
                const float* src = SPLIT
                    ? ((r < NCOLS/2) ? (WgA + r*K) : (WgB + (r - NCOLS/2)*K))
                    : (WgA + r*K);
                pf[t] = __ldg(reinterpret_cast<const float4*>(src + k0 + KB + kk4));
            }
        }
        const float* w0  = ws + c0*WSP;
        const float* w1  = w0 + WSP;
        const float* inb = inT + k0*LDT + m0;
#pragma unroll
        for (int kk4 = 0; kk4 < KB; kk4 += 4) {
            float4 wa = *reinterpret_cast<const float4*>(w0 + kk4);
            float4 wb = *reinterpret_cast<const float4*>(w1 + kk4);
            float wav[4] = {wa.x, wa.y, wa.z, wa.w};
            float wbv[4] = {wb.x, wb.y, wb.z, wb.w};
#pragma unroll
            for (int kk = 0; kk < 4; ++kk) {
                ull ba = bcast2(wav[kk]);
                ull bb = bcast2(wbv[kk]);
                const ulonglong2* p =
                    reinterpret_cast<const ulonglong2*>(inb + (kk4 + kk)*LDT);
#pragma unroll
                for (int j = 0; j < RPT/4; ++j) {
                    ulonglong2 v = p[j];
                    acc0[2*j]   = ffma2(v.x, ba, acc0[2*j]);
                    acc0[2*j+1] = ffma2(v.y, ba, acc0[2*j+1]);
                    acc1[2*j]   = ffma2(v.x, bb, acc1[2*j]);
                    acc1[2*j+1] = ffma2(v.y, bb, acc1[2*j+1]);
                }
            }
        }
    }
#pragma unroll
    for (int j = 0; j < RPT/2; ++j) {
        float2 f0 = unpack2(acc0[j]);
        out[2*j] = f0.x; out[2*j+1] = f0.y;
        float2 f1 = unpack2(acc1[j]);
        out[RPT + 2*j] = f1.x; out[RPT + 2*j+1] = f1.y;
    }
}

// LayerNorm of xs[MROWS][HID]. 16 lanes per row (2 rows per warp).
template<bool TRANS>
__device__ __forceinline__ void layer_norm(const float* __restrict__ xs,
                                           float* __restrict__ dst,
                                           const float* __restrict__ gw,
                                           const float* __restrict__ bw,
                                           int tid)
{
    int warp = tid >> 5, lane = tid & 31;
    int m   = warp*2 + (lane >> 4);
    int sub = lane & 15;
    const float* row = xs + m*HID + sub*16;
    float v[16];
#pragma unroll
    for (int i = 0; i < 4; ++i) {
        float4 t = *reinterpret_cast<const float4*>(row + i*4);
        v[4*i] = t.x; v[4*i+1] = t.y; v[4*i+2] = t.z; v[4*i+3] = t.w;
    }
    float s = 0.f;
#pragma unroll
    for (int i = 0; i < 16; ++i) s += v[i];
#pragma unroll
    for (int o = 8; o >= 1; o >>= 1) s += __shfl_xor_sync(0xffffffffu, s, o);
    float mean = s * (1.0f/HID);
    float q = 0.f;
#pragma unroll
    for (int i = 0; i < 16; ++i) { float d = v[i] - mean; q += d*d; }
#pragma unroll
    for (int o = 8; o >= 1; o >>= 1) q += __shfl_xor_sync(0xffffffffu, q, o);
    float rstd = rsqrtf(q * (1.0f/HID) + EPSV);
    int h0 = sub*16;
#pragma unroll
    for (int i = 0; i < 16; ++i) {
        float y = (v[i] - mean) * rstd * gw[h0+i] + bw[h0+i];
        if (TRANS) dst[(h0+i)*LDT + m] = y;
        else       dst[m*HID + h0 + i] = y;
    }
}

__global__ void __launch_bounds__(NTHREADS, 1)
mamba_fused_kernel(const float* __restrict__ data,
                   const float* __restrict__ in_w,  const float* __restrict__ in_b,
                   const float* __restrict__ norm_g,const float* __restrict__ norm_b,
                   const float* __restrict__ A_w,   const float* __restrict__ B_w,
                   const float* __restrict__ C_w,
                   const float* __restrict__ D_w,   const float* __restrict__ D_b,
                   const float* __restrict__ gate_w,const float* __restrict__ gate_b,
                   const float* __restrict__ ffn_w1,const float* __restrict__ ffn_b1,
                   const float* __restrict__ ffn_w2,const float* __restrict__ ffn_b2,
                   const float* __restrict__ fln_g, const float* __restrict__ fln_b,
                   const float* __restrict__ out_w, const float* __restrict__ out_b,
                   const float* __restrict__ cls_w, const float* __restrict__ cls_b,
                   const float* __restrict__ attn_w,const float* __restrict__ attn_b,
                   float* __restrict__ out)
{
    extern __shared__ float sm[];
    float* xs  = sm + OFF_XS;
    float* gs  = sm + OFF_GS;
    float* yt  = sm + OFF_YT;
    float* mid = sm + OFF_MID;
    float* at  = sm + OFF_AB;
    float* btt = at + DSTATE*LDT;
    float* ws  = sm + OFF_WS;

    const int tid = threadIdx.x;
    const int b0  = blockIdx.x * BT;

    // ---- load input rows [32][512] transposed into mid (as datat[k][m]) ----
    {
        const float4* gdat4 =
            reinterpret_cast<const float4*>(data + (size_t)b0 * S_SEQ * INDIM);
#pragma unroll
        for (int i = 0; i < (MROWS*INDIM/4)/NTHREADS; ++i) {
            int idx = tid + i*NTHREADS;
            float4 v = __ldg(gdat4 + idx);
            int lin = idx * 4;
            int m = lin >> 9;          // /512
            int k = lin & (INDIM-1);
            mid[(k+0)*LDT + m] = v.x;
            mid[(k+1)*LDT + m] = v.y;
            mid[(k+2)*LDT + m] = v.z;
            mid[(k+3)*LDT + m] = v.w;
        }
    }

    // standard mapping: 2 cols x 8 rows per thread
    const int c0 = 2 * (tid & 127);
    const int m0 = (tid >> 7) * 8;
    // A/B mapping: 2 cols x 4 rows per thread
    const int c0ab = 2 * (tid & 63);
    const int m0ab = (tid >> 6) * 4;

    // ---- input projection: xs = data @ in_w.T + in_b ----
    {
        float o[16];
        gemm2<HID, 8, false>(in_w, nullptr, INDIM, mid, m0, c0, ws, o, tid);
        float2 bias = *reinterpret_cast<const float2*>(in_b + c0);
#pragma unroll
        for (int j = 0; j < 8; ++j) {
            float2 v; v.x = o[j] + bias.x; v.y = o[8+j] + bias.y;
            *reinterpret_cast<float2*>(xs + (m0+j)*HID + c0) = v;
        }
    }
    __syncthreads();

    // ---------------- 6 layers ----------------
    for (int l = 0; l < NLAYER; ++l) {
        const float* ng = norm_g + l*HID;
        const float* nb = norm_b + l*HID;

        layer_norm<true>(xs, yt, ng, nb, tid);
        // gate = sigmoid(y @ gate_w.T + gate_b)   (gemm2 lead barrier covers yt)
        {
            float o[16];
            gemm2<HID, 8, false>(gate_w + l*HID*HID, nullptr, HID, yt, m0, c0, ws, o, tid);
            float2 bias = *reinterpret_cast<const float2*>(gate_b + l*HID + c0);
#pragma unroll
            for (int j = 0; j < 8; ++j) {
                float2 v;
                v.x = 1.0f / (1.0f + expf(-(o[j]   + bias.x)));
                v.y = 1.0f / (1.0f + expf(-(o[8+j] + bias.y)));
                *reinterpret_cast<float2*>(gs + (m0+j)*HID + c0) = v;
            }
        }
        // dt = y @ D_w.T + D_b ; xs += dt * (1 - g)  (same-thread gs, no sync)
        {
            float o[16];
            gemm2<HID, 8, false>(D_w + l*HID*HID, nullptr, HID, yt, m0, c0, ws, o, tid);
            float2 bias = *reinterpret_cast<const float2*>(D_b + l*HID + c0);
#pragma unroll
            for (int j = 0; j < 8; ++j) {
                int m = m0 + j;
                float2 g = *reinterpret_cast<const float2*>(gs + m*HID + c0);
                float2 x = *reinterpret_cast<const float2*>(xs + m*HID + c0);
                x.x += (o[j]   + bias.x) * (1.0f - g.x);
                x.y += (o[8+j] + bias.y) * (1.0f - g.y);
                *reinterpret_cast<float2*>(xs + m*HID + c0) = x;
            }
        }
        // a = tanh(y @ A_w.T), bt = y @ B_w.T  (128 combined cols, 2x4 per thread)
        {
            float o[8];
            gemm2<2*DSTATE, 4, true>(A_w + l*DSTATE*HID, B_w + l*DSTATE*HID,
                                     HID, yt, m0ab, c0ab, ws, o, tid);
            if (c0ab < DSTATE) {
                float4 v0, v1;
                v0.x = tanhf(o[0]); v0.y = tanhf(o[1]); v0.z = tanhf(o[2]); v0.w = tanhf(o[3]);
                v1.x = tanhf(o[4]); v1.y = tanhf(o[5]); v1.z = tanhf(o[6]); v1.w = tanhf(o[7]);
                *reinterpret_cast<float4*>(at + c0ab*LDT + m0ab)       = v0;
                *reinterpret_cast<float4*>(at + (c0ab+1)*LDT + m0ab)   = v1;
            } else {
                int d = c0ab - DSTATE;
                *reinterpret_cast<float4*>(btt + d*LDT + m0ab)     = make_float4(o[0],o[1],o[2],o[3]);
                *reinterpret_cast<float4*>(btt + (d+1)*LDT + m0ab) = make_float4(o[4],o[5],o[6],o[7]);
            }
        }
        __syncthreads();

        // scan: h = a*h + bt over s, in place into at (becomes hs)
        if (tid < BT*DSTATE) {
            int e = tid / DSTATE, d = tid % DSTATE;
            float h = 0.f;
#pragma unroll
            for (int s = 0; s < S_SEQ; ++s) {
                int m = e*S_SEQ + s;
                h = at[d*LDT + m] * h + btt[d*LDT + m];
                at[d*LDT + m] = h;
            }
        }
        __syncthreads();

        // ys = hs @ C_w.T ; xs += ys * g
        {
            float o[16];
            gemm2<HID, 8, false>(C_w + l*HID*DSTATE, nullptr, DSTATE, at, m0, c0, ws, o, tid);
#pragma unroll
            for (int j = 0; j < 8; ++j) {
                int m = m0 + j;
                float2 g = *reinterpret_cast<const float2*>(gs + m*HID + c0);
                float2 x = *reinterpret_cast<const float2*>(xs + m*HID + c0);
                x.x += o[j]   * g.x;
                x.y += o[8+j] * g.y;
                *reinterpret_cast<float2*>(xs + m*HID + c0) = x;
            }
        }
        __syncthreads();

        // FFN
        layer_norm<true>(xs, yt, ng, nb, tid);
        // mid = gelu(y @ w1.T + b1), two 256-column passes
#pragma unroll
        for (int pass = 0; pass < 2; ++pass) {
            float o[16];
            gemm2<HID, 8, false>(ffn_w1 + l*FF*HID + pass*256*HID, nullptr, HID,
                                 yt, m0, c0, ws, o, tid);
            float2 bias = *reinterpret_cast<const float2*>(ffn_b1 + l*FF + pass*256 + c0);
            float4 u0, u1;
            u0.x = gelu_exact(o[0] + bias.x); u0.y = gelu_exact(o[1] + bias.x);
            u0.z = gelu_exact(o[2] + bias.x); u0.w = gelu_exact(o[3] + bias.x);
            u1.x = gelu_exact(o[4] + bias.x); u1.y = gelu_exact(o[5] + bias.x);
            u1.z = gelu_exact(o[6] + bias.x); u1.w = gelu_exact(o[7] + bias.x);
            float* dst0 = mid + (pass*256 + c0)*LDT + m0;
            *reinterpret_cast<float4*>(dst0)     = u0;
            *reinterpret_cast<float4*>(dst0 + 4) = u1;
            float4 w0, w1;
            w0.x = gelu_exact(o[8]  + bias.y); w0.y = gelu_exact(o[9]  + bias.y);
            w0.z = gelu_exact(o[10] + bias.y); w0.w = gelu_exact(o[11] + bias.y);
            w1.x = gelu_exact(o[12] + bias.y); w1.y = gelu_exact(o[13] + bias.y);
            w1.z = gelu_exact(o[14] + bias.y); w1.w = gelu_exact(o[15] + bias.y);
            float* dst1 = mid + (pass*256 + c0 + 1)*LDT + m0;
            *reinterpret_cast<float4*>(dst1)     = w0;
            *reinterpret_cast<float4*>(dst1 + 4) = w1;
        }
        // xs += mid @ w2.T + b2   (gemm2 lead barrier covers mid)
        {
            float o[16];
            gemm2<HID, 8, false>(ffn_w2 + l*HID*FF, nullptr, FF, mid, m0, c0, ws, o, tid);
            float2 bias = *reinterpret_cast<const float2*>(ffn_b2 + l*HID + c0);
#pragma unroll
            for (int j = 0; j < 8; ++j) {
                int m = m0 + j;
                float2 x = *reinterpret_cast<const float2*>(xs + m*HID + c0);
                x.x += o[j]   + bias.x;
                x.y += o[8+j] + bias.y;
                *reinterpret_cast<float2*>(xs + m*HID + c0) = x;
            }
        }
        __syncthreads();
    }

    // ---------------- head ----------------
    layer_norm<false>(xs, gs, fln_g, fln_b, tid);   // gs = final LN, row-major
    __syncthreads();

    float* red    = mid;            // reuse mid as head scratch
    float* scores = red;            // [BT][16] (slots 0..14 used)
    float* wts    = red + 32;       // [BT][16]
    float* ov     = red + 64;       // [BT][HID]
    float* rr     = ov + BT*HID;    // [BT][128]
    float* zz     = rr + BT*128;    // [BT][NCLS]
    float* lse    = zz + BT*NCLS;   // [BT]

    {   // attention scores: warp w handles neighbor s=w+1 for both elements
        int warp = tid >> 5, lane = tid & 31;
        if (warp < 15) {
            for (int e = 0; e < BT; ++e) {
                const float* y0 = gs + (e*S_SEQ)*HID;
                const float* ysn = gs + (e*S_SEQ + warp + 1)*HID;
                float ssum = 0.f;
                for (int i = lane; i < HID; i += 32)
                    ssum += y0[i]*attn_w[i] + ysn[i]*attn_w[HID + i];
#pragma unroll
                for (int o = 16; o >= 1; o >>= 1)
                    ssum += __shfl_xor_sync(0xffffffffu, ssum, o);
                if (lane == 0) scores[e*16 + warp] = ssum + attn_b[0];
            }
        }
    }
    __syncthreads();
    if (tid < BT) {  // softmax over 15 neighbors
        int e = tid;
        float mx = -1e30f;
        for (int s = 0; s < 15; ++s) mx = fmaxf(mx, scores[e*16 + s]);
        float sum = 0.f;
        for (int s = 0; s < 15; ++s) sum += expf(scores[e*16 + s] - mx);
        float inv = 1.0f / sum;
        for (int s = 0; s < 15; ++s) wts[e*16 + s] = expf(scores[e*16 + s] - mx) * inv;
    }
    __syncthreads();
    {   // out_vec = node + sum_s nbr[s]*w[s]
        int e = tid >> 8, h = tid & 255;
        float v = gs[(e*S_SEQ)*HID + h];
#pragma unroll
        for (int s = 1; s < S_SEQ; ++s)
            v += gs[(e*S_SEQ + s)*HID + h] * wts[e*16 + s - 1];
        ov[e*HID + h] = v;
    }
    __syncthreads();
    if (tid < BT*128) {  // fc1 + relu
        int e = tid >> 7, j = tid & 127;
        const float* w = out_w + j*HID;
        float acc = out_b[j];
        for (int h = 0; h < HID; ++h) acc += ov[e*HID + h] * w[h];
        rr[e*128 + j] = fmaxf(acc, 0.f);
    }
    __syncthreads();
    if (tid < BT*NCLS) {  // classifier
        int e = tid / NCLS, cc = tid % NCLS;
        const float* w = cls_w + cc*128;
        float acc = cls_b[cc];
        for (int j = 0; j < 128; ++j) acc += rr[e*128 + j] * w[j];
        zz[e*NCLS + cc] = acc;
    }
    __syncthreads();
    if (tid < BT) {  // logsumexp
        int e = tid;
        float mx = -1e30f;
        for (int cc = 0; cc < NCLS; ++cc) mx = fmaxf(mx, zz[e*NCLS + cc]);
        float sum = 0.f;
        for (int cc = 0; cc < NCLS; ++cc) sum += expf(zz[e*NCLS + cc] - mx);
        lse[e] = mx + logf(sum);
    }
    __syncthreads();
    if (tid < BT*NCLS) {
        int e = tid / NCLS, cc = tid % NCLS;
        out[(size_t)(b0 + e)*NCLS + cc] = zz[e*NCLS + cc] - lse[e];
    }
}

extern "C" void kernel_launch(void* const* d_in, const int* in_sizes, int n_in,
                              void* d_out, int out_size)
{
    const float* data   = (const float*)d_in[0];
    const float* in_w   = (const float*)d_in[1];
    const float* in_b   = (const float*)d_in[2];
    const float* norm_g = (const float*)d_in[3];
    const float* norm_b = (const float*)d_in[4];
    const float* A_w    = (const float*)d_in[5];
    const float* B_w    = (const float*)d_in[6];
    const float* C_w    = (const float*)d_in[7];
    const float* D_w    = (const float*)d_in[8];
    const float* D_b    = (const float*)d_in[9];
    const float* gate_w = (const float*)d_in[10];
    const float* gate_b = (const float*)d_in[11];
    const float* ffn_w1 = (const float*)d_in[12];
    const float* ffn_b1 = (const float*)d_in[13];
    const float* ffn_w2 = (const float*)d_in[14];
    const float* ffn_b2 = (const float*)d_in[15];
    const float* fln_g  = (const float*)d_in[16];
    const float* fln_b  = (const float*)d_in[17];
    const float* out_w  = (const float*)d_in[18];
    const float* out_b  = (const float*)d_in[19];
    const float* cls_w  = (const float*)d_in[20];
    const float* cls_b  = (const float*)d_in[21];
    const float* attn_w = (const float*)d_in[22];
    const float* attn_b = (const float*)d_in[23];
    float* out = (float*)d_out;

    int Btotal = in_sizes[0] / (S_SEQ * INDIM);
    int grid = Btotal / BT;

    cudaFuncSetAttribute(mamba_fused_kernel,
                         cudaFuncAttributeMaxDynamicSharedMemorySize,
                         SMEM_FLOATS * (int)sizeof(float));

    mamba_fused_kernel<<<grid, NTHREADS, SMEM_FLOATS * sizeof(float)>>>(
        data, in_w, in_b, norm_g, norm_b, A_w, B_w, C_w, D_w, D_b,
        gate_w, gate_b, ffn_w1, ffn_b1, ffn_w2, ffn_b2,
        fln_g, fln_b, out_w, out_b, cls_w, cls_b, attn_w, attn_b, out);
}

// round 8
// speedup vs baseline: 1.6747x; 1.1282x over previous
#include <cuda_runtime.h>
#include <math.h>

// ---------------- problem constants ----------------
#define S_SEQ   16
#define HID     256
#define INDIM   512
#define DSTATE  64
#define NLAYER  6
#define NCLS    40
#define FF      512
#define EPSV    1e-5f

// ---------------- kernel config --------------------
#define BT        2                 // batch elements per CTA
#define MROWS     (BT*S_SEQ)        // 32 rows
#define NTHREADS  512
#define KB        32                // k-chunk (floats) staged per round

// smem float offsets (all multiples of 2048 -> 128B-aligned bases)
#define OFF_XS   0                           // [32][256] residual, row-major swizzled
#define OFF_GS   (OFF_XS + MROWS*HID)        // [32][256] gate (swz) / final-LN (linear)
#define OFF_YS   (OFF_GS + MROWS*HID)        // [32][256] LN output, row-major swizzled
#define OFF_MID  (OFF_YS + MROWS*HID)        // [32][512] data / ffn mid, swizzled
#define OFF_AT   (OFF_MID + MROWS*FF)        // [32][64] a / hs, swizzled
#define OFF_BT   (OFF_AT + MROWS*DSTATE)     // [32][64] bt, swizzled
#define OFF_WS   (OFF_BT + MROWS*DSTATE)     // [256][KB] staged weights, swizzled
#define OFF_RED  (OFF_WS + 256*KB)           // head scratch
#define SMEM_FLOATS (OFF_RED + 1024)         // 54272 floats = 217088 B

typedef unsigned long long ull;

__device__ __forceinline__ ull ffma2(ull a, ull b, ull c) {
    ull d;
    asm("fma.rn.f32x2 %0, %1, %2, %3;" : "=l"(d) : "l"(a), "l"(b), "l"(c));
    return d;
}
__device__ __forceinline__ float2 unpack2(ull v) {
    float2 r;
    asm("mov.b64 {%0, %1}, %2;" : "=f"(r.x), "=f"(r.y) : "l"(v));
    return r;
}
__device__ __forceinline__ float gelu_exact(float x) {
    return 0.5f * x * (1.0f + erff(x * 0.70710678118654752f));
}

// byte offset of the float4 group holding col c (mult of 4) in a swizzled row-major
// tile: base_f float offset, row m, row-stride XS floats, swizzle (c>>2)^ (m&7)
__device__ __forceinline__ unsigned sw4(int base_f, int m, int XS, int c) {
    return (unsigned)((base_f + m*XS) * 4) + ((((unsigned)(c >> 2) ^ (unsigned)(m & 7)) << 4));
}

// ---- row-major k-pair GEMM -------------------------------------------------
// out[j*TC+jj] = sum_k x[m_j][k] * Wg[c0+jj][k],  m_j = mg + 8j (4 rows),
// TC cols per thread starting at c0. x tile: row-major swizzled smem at
// float-offset xoff_f with row stride XS. Weights: global [NCOLS][K] row-major,
// staged per 32-float chunk into ws (swizzled), register-prefetched.
// ALL 512 threads must call (barriers inside).
template<int NCOLS, int TC, bool SPLIT>
__device__ __forceinline__ void gemmK(const float* __restrict__ WgA,
                                      const float* __restrict__ WgB,
                                      int K, int xoff_f, int XS,
                                      float* __restrict__ sm,
                                      float* __restrict__ out,
                                      int tid, int mg, int c0)
{
    constexpr int PF = NCOLS / 64;           // float4 staged per thread per chunk
    char* smb = (char*)sm;
    const unsigned wsbyte = OFF_WS * 4;

    ull acc[4][TC];
#pragma unroll
    for (int j = 0; j < 4; ++j)
#pragma unroll
        for (int jj = 0; jj < TC; ++jj) acc[j][jj] = 0ull;

    // swizzle-folded byte offsets (bases are 128B-aligned, xor bits < 128)
    unsigned xoff[4];
#pragma unroll
    for (int j = 0; j < 4; ++j)
        xoff[j] = (unsigned)((xoff_f + (mg + 8*j)*XS) * 4) ^ (unsigned)(mg << 4);
    unsigned woff[TC];
#pragma unroll
    for (int jj = 0; jj < TC; ++jj) {
        unsigned c = (unsigned)(c0 + jj);
        woff[jj] = (wsbyte + c*KB*4) ^ (((c >> 1) & 7u) << 4);
    }

    float4 pf[PF];
#pragma unroll
    for (int t = 0; t < PF; ++t) {
        int i = tid + t*NTHREADS;
        int r = i >> 3, kk4 = i & 7;
        const float* src = SPLIT ? ((r < NCOLS/2) ? WgA + r*K : WgB + (r - NCOLS/2)*K)
                                 : WgA + r*K;
        pf[t] = __ldg(reinterpret_cast<const float4*>(src + kk4*4));
    }

    for (int k0 = 0; k0 < K; k0 += KB) {
        __syncthreads();   // prior ws consumers / x producers done
#pragma unroll
        for (int t = 0; t < PF; ++t) {
            int i = tid + t*NTHREADS;
            int r = i >> 3, kk4 = i & 7;
            unsigned soff = (wsbyte + (unsigned)r*KB*4)
                          + (((unsigned)(kk4 ^ ((r >> 1) & 7)) << 4));
            *reinterpret_cast<float4*>(smb + soff) = pf[t];
        }
        __syncthreads();
        if (k0 + KB < K) {   // prefetch next chunk, overlaps compute
#pragma unroll
            for (int t = 0; t < PF; ++t) {
                int i = tid + t*NTHREADS;
                int r = i >> 3, kk4 = i & 7;
                const float* src = SPLIT ? ((r < NCOLS/2) ? WgA + r*K : WgB + (r - NCOLS/2)*K)
                                         : WgA + r*K;
                pf[t] = __ldg(reinterpret_cast<const float4*>(src + k0 + KB + kk4*4));
            }
        }
#pragma unroll
        for (int kk4 = 0; kk4 < KB/4; ++kk4) {
            unsigned kx = (unsigned)(kk4 << 4);
            ulonglong2 xv[4];
#pragma unroll
            for (int j = 0; j < 4; ++j)
                xv[j] = *reinterpret_cast<const ulonglong2*>(smb + (xoff[j] ^ kx));
            ulonglong2 wv[TC];
#pragma unroll
            for (int jj = 0; jj < TC; ++jj)
                wv[jj] = *reinterpret_cast<const ulonglong2*>(smb + (woff[jj] ^ kx));
#pragma unroll
            for (int j = 0; j < 4; ++j)
#pragma unroll
                for (int jj = 0; jj < TC; ++jj) {
                    acc[j][jj] = ffma2(xv[j].x, wv[jj].x, acc[j][jj]);
                    acc[j][jj] = ffma2(xv[j].y, wv[jj].y, acc[j][jj]);
                }
        }
#pragma unroll
        for (int j = 0; j < 4; ++j) xoff[j] += KB*4;
    }
#pragma unroll
    for (int j = 0; j < 4; ++j)
#pragma unroll
        for (int jj = 0; jj < TC; ++jj) {
            float2 f = unpack2(acc[j][jj]);
            out[j*TC + jj] = f.x + f.y;
        }
}

// LayerNorm: reads swizzled xs rows, writes ys (swizzled) or gs (linear).
template<bool SWZ_OUT>
__device__ __forceinline__ void layer_norm2(float* __restrict__ sm,
                                            int src_f, int dst_f,
                                            const float* __restrict__ gw,
                                            const float* __restrict__ bw,
                                            int tid)
{
    char* smb = (char*)sm;
    int warp = tid >> 5, lane = tid & 31;
    int m   = warp*2 + (lane >> 4);
    int sub = lane & 15;
    unsigned swm = (unsigned)(m & 7);
    unsigned rb = (unsigned)((src_f + m*HID) * 4);
    float v[16];
#pragma unroll
    for (int i = 0; i < 4; ++i) {
        unsigned k4 = (unsigned)(sub*4 + i);
        float4 t = *reinterpret_cast<const float4*>(smb + rb + ((k4 ^ swm) << 4));
        v[4*i] = t.x; v[4*i+1] = t.y; v[4*i+2] = t.z; v[4*i+3] = t.w;
    }
    float s = 0.f;
#pragma unroll
    for (int i = 0; i < 16; ++i) s += v[i];
#pragma unroll
    for (int o = 8; o >= 1; o >>= 1) s += __shfl_xor_sync(0xffffffffu, s, o);
    float mean = s * (1.0f/HID);
    float q = 0.f;
#pragma unroll
    for (int i = 0; i < 16; ++i) { float d = v[i] - mean; q += d*d; }
#pragma unroll
    for (int o = 8; o >= 1; o >>= 1) q += __shfl_xor_sync(0xffffffffu, q, o);
    float rstd = rsqrtf(q * (1.0f/HID) + EPSV);
    int h0 = sub*16;
    unsigned wb = (unsigned)((dst_f + m*HID) * 4);
#pragma unroll
    for (int i = 0; i < 4; ++i) {
        float4 y;
        y.x = (v[4*i+0] - mean)*rstd*gw[h0+4*i+0] + bw[h0+4*i+0];
        y.y = (v[4*i+1] - mean)*rstd*gw[h0+4*i+1] + bw[h0+4*i+1];
        y.z = (v[4*i+2] - mean)*rstd*gw[h0+4*i+2] + bw[h0+4*i+2];
        y.w = (v[4*i+3] - mean)*rstd*gw[h0+4*i+3] + bw[h0+4*i+3];
        unsigned k4 = (unsigned)(sub*4 + i);
        unsigned off = SWZ_OUT ? (wb + ((k4 ^ swm) << 4)) : (wb + (k4 << 4));
        *reinterpret_cast<float4*>(smb + off) = y;
    }
}

__global__ void __launch_bounds__(NTHREADS, 1)
mamba_fused_kernel(const float* __restrict__ data,
                   const float* __restrict__ in_w,  const float* __restrict__ in_b,
                   const float* __restrict__ norm_g,const float* __restrict__ norm_b,
                   const float* __restrict__ A_w,   const float* __restrict__ B_w,
                   const float* __restrict__ C_w,
                   const float* __restrict__ D_w,   const float* __restrict__ D_b,
                   const float* __restrict__ gate_w,const float* __restrict__ gate_b,
                   const float* __restrict__ ffn_w1,const float* __restrict__ ffn_b1,
                   const float* __restrict__ ffn_w2,const float* __restrict__ ffn_b2,
                   const float* __restrict__ fln_g, const float* __restrict__ fln_b,
                   const float* __restrict__ out_w, const float* __restrict__ out_b,
                   const float* __restrict__ cls_w, const float* __restrict__ cls_b,
                   const float* __restrict__ attn_w,const float* __restrict__ attn_b,
                   float* __restrict__ out)
{
    extern __shared__ float sm[];
    char* smb = (char*)sm;
    float* gs  = sm + OFF_GS;
    float* red = sm + OFF_RED;

    const int tid = threadIdx.x;
    const int b0  = blockIdx.x * BT;

    const int lane = tid & 31, warp = tid >> 5;
    const int mg = lane & 7, cg = lane >> 3;
    const int c0   = warp*16 + cg*4;    // main mapping: 4 cols
    const int c0ab = warp*8  + cg*2;    // AB mapping: 2 cols

    // ---- load input [32][512] row-major swizzled into mid ----
    {
        const float4* gdat4 =
            reinterpret_cast<const float4*>(data + (size_t)b0 * S_SEQ * INDIM);
#pragma unroll
        for (int i = 0; i < (MROWS*INDIM/4)/NTHREADS; ++i) {
            int idx = tid + i*NTHREADS;
            float4 v = __ldg(gdat4 + idx);
            int lin = idx * 4;
            int m = lin >> 9;              // /512
            int k4 = (lin & (INDIM-1)) >> 2;
            unsigned off = (unsigned)((OFF_MID + m*FF)*4)
                         + (((unsigned)(k4 ^ (m & 7))) << 4);
            *reinterpret_cast<float4*>(smb + off) = v;
        }
    }

    // ---- input projection: xs = data @ in_w.T + in_b ----
    {
        float o[16];
        gemmK<256,4,false>(in_w, nullptr, INDIM, OFF_MID, FF, sm, o, tid, mg, c0);
        float4 bias = *reinterpret_cast<const float4*>(in_b + c0);
#pragma unroll
        for (int j = 0; j < 4; ++j) {
            int m = mg + 8*j;
            float4 v = make_float4(o[j*4]+bias.x, o[j*4+1]+bias.y,
                                   o[j*4+2]+bias.z, o[j*4+3]+bias.w);
            *reinterpret_cast<float4*>(smb + sw4(OFF_XS, m, HID, c0)) = v;
        }
    }
    __syncthreads();

    // ---------------- 6 layers ----------------
    for (int l = 0; l < NLAYER; ++l) {
        const float* ng = norm_g + l*HID;
        const float* nb = norm_b + l*HID;

        layer_norm2<true>(sm, OFF_XS, OFF_YS, ng, nb, tid);
        // gate = sigmoid(y @ gate_w.T + gate_b)  (gemmK lead barrier covers ys)
        float gv[16];
        {
            float o[16];
            gemmK<256,4,false>(gate_w + l*HID*HID, nullptr, HID, OFF_YS, HID, sm, o, tid, mg, c0);
            float4 bias = *reinterpret_cast<const float4*>(gate_b + l*HID + c0);
#pragma unroll
            for (int j = 0; j < 4; ++j) {
                int m = mg + 8*j;
                float4 v;
                v.x = 1.0f/(1.0f + expf(-(o[j*4]  +bias.x)));
                v.y = 1.0f/(1.0f + expf(-(o[j*4+1]+bias.y)));
                v.z = 1.0f/(1.0f + expf(-(o[j*4+2]+bias.z)));
                v.w = 1.0f/(1.0f + expf(-(o[j*4+3]+bias.w)));
                gv[j*4]=v.x; gv[j*4+1]=v.y; gv[j*4+2]=v.z; gv[j*4+3]=v.w;
                *reinterpret_cast<float4*>(smb + sw4(OFF_GS, m, HID, c0)) = v;
            }
        }
        // dt = y @ D_w.T + D_b ; xs += dt * (1 - g)
        {
            float o[16];
            gemmK<256,4,false>(D_w + l*HID*HID, nullptr, HID, OFF_YS, HID, sm, o, tid, mg, c0);
            float4 bias = *reinterpret_cast<const float4*>(D_b + l*HID + c0);
#pragma unroll
            for (int j = 0; j < 4; ++j) {
                int m = mg + 8*j;
                unsigned offx = sw4(OFF_XS, m, HID, c0);
                float4 x = *reinterpret_cast<const float4*>(smb + offx);
                x.x += (o[j*4]  +bias.x)*(1.0f-gv[j*4]);
                x.y += (o[j*4+1]+bias.y)*(1.0f-gv[j*4+1]);
                x.z += (o[j*4+2]+bias.z)*(1.0f-gv[j*4+2]);
                x.w += (o[j*4+3]+bias.w)*(1.0f-gv[j*4+3]);
                *reinterpret_cast<float4*>(smb + offx) = x;
            }
        }
        // a = tanh(y @ A_w.T), bt = y @ B_w.T  (combined 128 cols, 2 per thread)
        {
            float o[8];
            gemmK<128,2,true>(A_w + l*DSTATE*HID, B_w + l*DSTATE*HID,
                              HID, OFF_YS, HID, sm, o, tid, mg, c0ab);
            bool isA = (c0ab < DSTATE);
            int d0 = isA ? c0ab : (c0ab - DSTATE);
            int base = isA ? OFF_AT : OFF_BT;
#pragma unroll
            for (int j = 0; j < 4; ++j) {
                int m = mg + 8*j;
                float2 v;
                if (isA) { v.x = tanhf(o[j*2]); v.y = tanhf(o[j*2+1]); }
                else     { v.x = o[j*2];        v.y = o[j*2+1]; }
                unsigned off = (unsigned)((base + m*DSTATE)*4)
                             + (((unsigned)((d0 >> 2) ^ (m & 7))) << 4)
                             + ((unsigned)(d0 & 3) << 2);
                *reinterpret_cast<float2*>(smb + off) = v;
            }
        }
        __syncthreads();

        // scan: h = a*h + bt over s, in place into at (becomes hs)
        if (tid < BT*DSTATE) {
            int e = tid >> 6, d = tid & (DSTATE-1);
            float h = 0.f;
#pragma unroll
            for (int s = 0; s < S_SEQ; ++s) {
                int m = e*S_SEQ + s;
                unsigned off = (unsigned)((OFF_AT + m*DSTATE)*4)
                             + (((unsigned)((d >> 2) ^ (m & 7))) << 4)
                             + ((unsigned)(d & 3) << 2);
                float a = *reinterpret_cast<const float*>(smb + off);
                float b = *reinterpret_cast<const float*>(smb + off + (OFF_BT-OFF_AT)*4);
                h = a*h + b;
                *reinterpret_cast<float*>(smb + off) = h;
            }
        }
        __syncthreads();

        // ys = hs @ C_w.T ; xs += ys * g
        {
            float o[16];
            gemmK<256,4,false>(C_w + l*HID*DSTATE, nullptr, DSTATE, OFF_AT, DSTATE, sm, o, tid, mg, c0);
#pragma unroll
            for (int j = 0; j < 4; ++j) {
                int m = mg + 8*j;
                unsigned offx = sw4(OFF_XS, m, HID, c0);
                float4 x = *reinterpret_cast<const float4*>(smb + offx);
                x.x += o[j*4]  *gv[j*4];
                x.y += o[j*4+1]*gv[j*4+1];
                x.z += o[j*4+2]*gv[j*4+2];
                x.w += o[j*4+3]*gv[j*4+3];
                *reinterpret_cast<float4*>(smb + offx) = x;
            }
        }
        __syncthreads();

        // FFN
        layer_norm2<true>(sm, OFF_XS, OFF_YS, ng, nb, tid);
        // mid = gelu(y @ w1.T + b1), two 256-col passes
#pragma unroll
        for (int pass = 0; pass < 2; ++pass) {
            float o[16];
            gemmK<256,4,false>(ffn_w1 + l*FF*HID + pass*256*HID, nullptr, HID,
                               OFF_YS, HID, sm, o, tid, mg, c0);
            float4 bias = *reinterpret_cast<const float4*>(ffn_b1 + l*FF + pass*256 + c0);
#pragma unroll
            for (int j = 0; j < 4; ++j) {
                int m = mg + 8*j;
                float4 v;
                v.x = gelu_exact(o[j*4]  +bias.x);
                v.y = gelu_exact(o[j*4+1]+bias.y);
                v.z = gelu_exact(o[j*4+2]+bias.z);
                v.w = gelu_exact(o[j*4+3]+bias.w);
                *reinterpret_cast<float4*>(smb + sw4(OFF_MID, m, FF, pass*256 + c0)) = v;
            }
        }
        // xs += mid @ w2.T + b2  (gemmK lead barrier covers mid)
        {
            float o[16];
            gemmK<256,4,false>(ffn_w2 + l*HID*FF, nullptr, FF, OFF_MID, FF, sm, o, tid, mg, c0);
            float4 bias = *reinterpret_cast<const float4*>(ffn_b2 + l*HID + c0);
#pragma unroll
            for (int j = 0; j < 4; ++j) {
                int m = mg + 8*j;
                unsigned offx = sw4(OFF_XS, m, HID, c0);
                float4 x = *reinterpret_cast<const float4*>(smb + offx);
                x.x += o[j*4]  +bias.x;
                x.y += o[j*4+1]+bias.y;
                x.z += o[j*4+2]+bias.z;
                x.w += o[j*4+3]+bias.w;
                *reinterpret_cast<float4*>(smb + offx) = x;
            }
        }
        __syncthreads();
    }

    // ---------------- head ----------------
    layer_norm2<false>(sm, OFF_XS, OFF_GS, fln_g, fln_b, tid);  // gs linear
    __syncthreads();

    float* scores = red;            // [BT][16] (slots 0..14 used)
    float* wts    = red + 32;       // [BT][16]
    float* ov     = red + 64;       // [BT][HID]
    float* rr     = ov + BT*HID;    // [BT][128]
    float* zz     = rr + BT*128;    // [BT][NCLS]
    float* lse    = zz + BT*NCLS;   // [BT]

    {   // attention scores: warp w handles neighbor s=w+1 for both elements
        if (warp < 15) {
            for (int e = 0; e < BT; ++e) {
                const float* y0  = gs + (e*S_SEQ)*HID;
                const float* ysn = gs + (e*S_SEQ + warp + 1)*HID;
                float ssum = 0.f;
                for (int i = lane; i < HID; i += 32)
                    ssum += y0[i]*attn_w[i] + ysn[i]*attn_w[HID + i];
#pragma unroll
                for (int o = 16; o >= 1; o >>= 1)
                    ssum += __shfl_xor_sync(0xffffffffu, ssum, o);
                if (lane == 0) scores[e*16 + warp] = ssum + attn_b[0];
            }
        }
    }
    __syncthreads();
    if (tid < BT) {  // softmax over 15 neighbors
        int e = tid;
        float mx = -1e30f;
        for (int s = 0; s < 15; ++s) mx = fmaxf(mx, scores[e*16 + s]);
        float sum = 0.f;
        for (int s = 0; s < 15; ++s) sum += expf(scores[e*16 + s] - mx);
        float inv = 1.0f / sum;
        for (int s = 0; s < 15; ++s) wts[e*16 + s] = expf(scores[e*16 + s] - mx) * inv;
    }
    __syncthreads();
    {   // out_vec = node + sum_s nbr[s]*w[s]
        int e = tid >> 8, h = tid & 255;
        float v = gs[(e*S_SEQ)*HID + h];
#pragma unroll
        for (int s = 1; s < S_SEQ; ++s)
            v += gs[(e*S_SEQ + s)*HID + h] * wts[e*16 + s - 1];
        ov[e*HID + h] = v;
    }
    __syncthreads();
    if (tid < BT*128) {  // fc1 + relu
        int e = tid >> 7, j = tid & 127;
        const float* w = out_w + j*HID;
        float acc = out_b[j];
        for (int h = 0; h < HID; ++h) acc += ov[e*HID + h] * w[h];
        rr[e*128 + j] = fmaxf(acc, 0.f);
    }
    __syncthreads();
    if (tid < BT*NCLS) {  // classifier
        int e = tid / NCLS, cc = tid % NCLS;
        const float* w = cls_w + cc*128;
        float acc = cls_b[cc];
        for (int j = 0; j < 128; ++j) acc += rr[e*128 + j] * w[j];
        zz[e*NCLS + cc] = acc;
    }
    __syncthreads();
    if (tid < BT) {  // logsumexp
        int e = tid;
        float mx = -1e30f;
        for (int cc = 0; cc < NCLS; ++cc) mx = fmaxf(mx, zz[e*NCLS + cc]);
        float sum = 0.f;
        for (int cc = 0; cc < NCLS; ++cc) sum += expf(zz[e*NCLS + cc] - mx);
        lse[e] = mx + logf(sum);
    }
    __syncthreads();
    if (tid < BT*NCLS) {
        int e = tid / NCLS, cc = tid % NCLS;
        out[(size_t)(b0 + e)*NCLS + cc] = zz[e*NCLS + cc] - lse[e];
    }
}

extern "C" void kernel_launch(void* const* d_in, const int* in_sizes, int n_in,
                              void* d_out, int out_size)
{
    const float* data   = (const float*)d_in[0];
    const float* in_w   = (const float*)d_in[1];
    const float* in_b   = (const float*)d_in[2];
    const float* norm_g = (const float*)d_in[3];
    const float* norm_b = (const float*)d_in[4];
    const float* A_w    = (const float*)d_in[5];
    const float* B_w    = (const float*)d_in[6];
    const float* C_w    = (const float*)d_in[7];
    const float* D_w    = (const float*)d_in[8];
    const float* D_b    = (const float*)d_in[9];
    const float* gate_w = (const float*)d_in[10];
    const float* gate_b = (const float*)d_in[11];
    const float* ffn_w1 = (const float*)d_in[12];
    const float* ffn_b1 = (const float*)d_in[13];
    const float* ffn_w2 = (const float*)d_in[14];
    const float* ffn_b2 = (const float*)d_in[15];
    const float* fln_g  = (const float*)d_in[16];
    const float* fln_b  = (const float*)d_in[17];
    const float* out_w  = (const float*)d_in[18];
    const float* out_b  = (const float*)d_in[19];
    const float* cls_w  = (const float*)d_in[20];
    const float* cls_b  = (const float*)d_in[21];
    const float* attn_w = (const float*)d_in[22];
    const float* attn_b = (const float*)d_in[23];
    float* out = (float*)d_out;

    int Btotal = in_sizes[0] / (S_SEQ * INDIM);
    int grid = Btotal / BT;

    cudaFuncSetAttribute(mamba_fused_kernel,
                         cudaFuncAttributeMaxDynamicSharedMemorySize,
                         SMEM_FLOATS * (int)sizeof(float));

    mamba_fused_kernel<<<grid, NTHREADS, SMEM_FLOATS * sizeof(float)>>>(
        data, in_w, in_b, norm_g, norm_b, A_w, B_w, C_w, D_w, D_b,
        gate_w, gate_b, ffn_w1, ffn_b1, ffn_w2, ffn_b2,
        fln_g, fln_b, out_w, out_b, cls_w, cls_b, attn_w, attn_b, out);
}

// round 9
// speedup vs baseline: 1.6750x; 1.0002x over previous
#include <cuda_runtime.h>
#include <math.h>

// ---------------- problem constants ----------------
#define S_SEQ   16
#define HID     256
#define INDIM   512
#define DSTATE  64
#define NLAYER  6
#define NCLS    40
#define FF      512
#define EPSV    1e-5f

// ---------------- kernel config --------------------
#define BT        2                 // batch elements per CTA
#define MROWS     (BT*S_SEQ)        // 32 rows
#define NTHREADS  512
#define KB        32                // k-chunk (floats) staged per round

// smem float offsets (all multiples of 2048 -> 128B-aligned bases)
#define OFF_XS   0                           // [32][256] residual, row-major swizzled
#define OFF_GS   (OFF_XS + MROWS*HID)        // [32][256] gate (swz) / final-LN (linear)
#define OFF_YS   (OFF_GS + MROWS*HID)        // [32][256] LN output, row-major swizzled
#define OFF_MID  (OFF_YS + MROWS*HID)        // [32][512] data / ffn mid, swizzled
#define OFF_AT   (OFF_MID + MROWS*FF)        // [32][64] a / hs, swizzled
#define OFF_BT   (OFF_AT + MROWS*DSTATE)     // [32][64] bt, swizzled
#define OFF_WS   (OFF_BT + MROWS*DSTATE)     // [256][KB] staged weights, swizzled
#define OFF_RED  (OFF_WS + 256*KB)           // head scratch
#define SMEM_FLOATS (OFF_RED + 1024)         // 54272 floats = 217088 B

typedef unsigned long long ull;

__device__ __forceinline__ ull ffma2(ull a, ull b, ull c) {
    ull d;
    asm("fma.rn.f32x2 %0, %1, %2, %3;" : "=l"(d) : "l"(a), "l"(b), "l"(c));
    return d;
}
__device__ __forceinline__ float2 unpack2(ull v) {
    float2 r;
    asm("mov.b64 {%0, %1}, %2;" : "=f"(r.x), "=f"(r.y) : "l"(v));
    return r;
}
__device__ __forceinline__ float gelu_exact(float x) {
    return 0.5f * x * (1.0f + erff(x * 0.70710678118654752f));
}

// byte offset of the float4 group holding col c (mult of 4) in a swizzled row-major
// tile: base_f float offset, row m, row-stride XS floats, swizzle (c>>2)^ (m&7)
__device__ __forceinline__ unsigned sw4(int base_f, int m, int XS, int c) {
    return (unsigned)((base_f + m*XS) * 4) + ((((unsigned)(c >> 2) ^ (unsigned)(m & 7)) << 4));
}

// ---- row-major k-pair GEMM -------------------------------------------------
// out[j*TC+jj] = sum_k x[m_j][k] * Wg[c0+jj][k],  m_j = mg + 8j (4 rows),
// TC cols per thread starting at c0. x tile: row-major swizzled smem at
// float-offset xoff_f with row stride XS. Weights: global [NCOLS][K] row-major,
// staged per 32-float chunk into ws (swizzled), register-prefetched.
// ALL 512 threads must call (barriers inside).
template<int NCOLS, int TC, bool SPLIT>
__device__ __forceinline__ void gemmK(const float* __restrict__ WgA,
                                      const float* __restrict__ WgB,
                                      int K, int xoff_f, int XS,
                                      float* __restrict__ sm,
                                      float* __restrict__ out,
                                      int tid, int mg, int c0)
{
    constexpr int PF = NCOLS / 64;           // float4 staged per thread per chunk
    char* smb = (char*)sm;
    const unsigned wsbyte = OFF_WS * 4;

    ull acc[4][TC];
#pragma unroll
    for (int j = 0; j < 4; ++j)
#pragma unroll
        for (int jj = 0; jj < TC; ++jj) acc[j][jj] = 0ull;

    // swizzle-folded byte offsets (bases are 128B-aligned, xor bits < 128)
    unsigned xoff[4];
#pragma unroll
    for (int j = 0; j < 4; ++j)
        xoff[j] = (unsigned)((xoff_f + (mg + 8*j)*XS) * 4) ^ (unsigned)(mg << 4);
    unsigned woff[TC];
#pragma unroll
    for (int jj = 0; jj < TC; ++jj) {
        unsigned c = (unsigned)(c0 + jj);
        woff[jj] = (wsbyte + c*KB*4) ^ (((c >> 1) & 7u) << 4);
    }

    float4 pf[PF];
#pragma unroll
    for (int t = 0; t < PF; ++t) {
        int i = tid + t*NTHREADS;
        int r = i >> 3, kk4 = i & 7;
        const float* src = SPLIT ? ((r < NCOLS/2) ? WgA + r*K : WgB + (r - NCOLS/2)*K)
                                 : WgA + r*K;
        pf[t] = __ldg(reinterpret_cast<const float4*>(src + kk4*4));
    }

    for (int k0 = 0; k0 < K; k0 += KB) {
        __syncthreads();   // prior ws consumers / x producers done
#pragma unroll
        for (int t = 0; t < PF; ++t) {
            int i = tid + t*NTHREADS;
            int r = i >> 3, kk4 = i & 7;
            unsigned soff = (wsbyte + (unsigned)r*KB*4)
                          + (((unsigned)(kk4 ^ ((r >> 1) & 7)) << 4));
            *reinterpret_cast<float4*>(smb + soff) = pf[t];
        }
        __syncthreads();
        if (k0 + KB < K) {   // prefetch next chunk, overlaps compute
#pragma unroll
            for (int t = 0; t < PF; ++t) {
                int i = tid + t*NTHREADS;
                int r = i >> 3, kk4 = i & 7;
                const float* src = SPLIT ? ((r < NCOLS/2) ? WgA + r*K : WgB + (r - NCOLS/2)*K)
                                         : WgA + r*K;
                pf[t] = __ldg(reinterpret_cast<const float4*>(src + k0 + KB + kk4*4));
            }
        }
#pragma unroll
        for (int kk4 = 0; kk4 < KB/4; ++kk4) {
            unsigned kx = (unsigned)(kk4 << 4);
            ulonglong2 xv[4];
#pragma unroll
            for (int j = 0; j < 4; ++j)
                xv[j] = *reinterpret_cast<const ulonglong2*>(smb + (xoff[j] ^ kx));
            ulonglong2 wv[TC];
#pragma unroll
            for (int jj = 0; jj < TC; ++jj)
                wv[jj] = *reinterpret_cast<const ulonglong2*>(smb + (woff[jj] ^ kx));
#pragma unroll
            for (int j = 0; j < 4; ++j)
#pragma unroll
                for (int jj = 0; jj < TC; ++jj) {
                    acc[j][jj] = ffma2(xv[j].x, wv[jj].x, acc[j][jj]);
                    acc[j][jj] = ffma2(xv[j].y, wv[jj].y, acc[j][jj]);
                }
        }
#pragma unroll
        for (int j = 0; j < 4; ++j) xoff[j] += KB*4;
    }
#pragma unroll
    for (int j = 0; j < 4; ++j)
#pragma unroll
        for (int jj = 0; jj < TC; ++jj) {
            float2 f = unpack2(acc[j][jj]);
            out[j*TC + jj] = f.x + f.y;
        }
}

// LayerNorm: reads swizzled xs rows, writes ys (swizzled) or gs (linear).
template<bool SWZ_OUT>
__device__ __forceinline__ void layer_norm2(float* __restrict__ sm,
                                            int src_f, int dst_f,
                                            const float* __restrict__ gw,
                                            const float* __restrict__ bw,
                                            int tid)
{
    char* smb = (char*)sm;
    int warp = tid >> 5, lane = tid & 31;
    int m   = warp*2 + (lane >> 4);
    int sub = lane & 15;
    unsigned swm = (unsigned)(m & 7);
    unsigned rb = (unsigned)((src_f + m*HID) * 4);
    float v[16];
#pragma unroll
    for (int i = 0; i < 4; ++i) {
        unsigned k4 = (unsigned)(sub*4 + i);
        float4 t = *reinterpret_cast<const float4*>(smb + rb + ((k4 ^ swm) << 4));
        v[4*i] = t.x; v[4*i+1] = t.y; v[4*i+2] = t.z; v[4*i+3] = t.w;
    }
    float s = 0.f;
#pragma unroll
    for (int i = 0; i < 16; ++i) s += v[i];
#pragma unroll
    for (int o = 8; o >= 1; o >>= 1) s += __shfl_xor_sync(0xffffffffu, s, o);
    float mean = s * (1.0f/HID);
    float q = 0.f;
#pragma unroll
    for (int i = 0; i < 16; ++i) { float d = v[i] - mean; q += d*d; }
#pragma unroll
    for (int o = 8; o >= 1; o >>= 1) q += __shfl_xor_sync(0xffffffffu, q, o);
    float rstd = rsqrtf(q * (1.0f/HID) + EPSV);
    int h0 = sub*16;
    unsigned wb = (unsigned)((dst_f + m*HID) * 4);
#pragma unroll
    for (int i = 0; i < 4; ++i) {
        float4 y;
        y.x = (v[4*i+0] - mean)*rstd*gw[h0+4*i+0] + bw[h0+4*i+0];
        y.y = (v[4*i+1] - mean)*rstd*gw[h0+4*i+1] + bw[h0+4*i+1];
        y.z = (v[4*i+2] - mean)*rstd*gw[h0+4*i+2] + bw[h0+4*i+2];
        y.w = (v[4*i+3] - mean)*rstd*gw[h0+4*i+3] + bw[h0+4*i+3];
        unsigned k4 = (unsigned)(sub*4 + i);
        unsigned off = SWZ_OUT ? (wb + ((k4 ^ swm) << 4)) : (wb + (k4 << 4));
        *reinterpret_cast<float4*>(smb + off) = y;
    }
}

__global__ void __launch_bounds__(NTHREADS, 1)
mamba_fused_kernel(const float* __restrict__ data,
                   const float* __restrict__ in_w,  const float* __restrict__ in_b,
                   const float* __restrict__ norm_g,const float* __restrict__ norm_b,
                   const float* __restrict__ A_w,   const float* __restrict__ B_w,
                   const float* __restrict__ C_w,
                   const float* __restrict__ D_w,   const float* __restrict__ D_b,
                   const float* __restrict__ gate_w,const float* __restrict__ gate_b,
                   const float* __restrict__ ffn_w1,const float* __restrict__ ffn_b1,
                   const float* __restrict__ ffn_w2,const float* __restrict__ ffn_b2,
                   const float* __restrict__ fln_g, const float* __restrict__ fln_b,
                   const float* __restrict__ out_w, const float* __restrict__ out_b,
                   const float* __restrict__ cls_w, const float* __restrict__ cls_b,
                   const float* __restrict__ attn_w,const float* __restrict__ attn_b,
                   float* __restrict__ out)
{
    extern __shared__ float sm[];
    char* smb = (char*)sm;
    float* gs  = sm + OFF_GS;
    float* red = sm + OFF_RED;

    const int tid = threadIdx.x;
    const int b0  = blockIdx.x * BT;

    const int lane = tid & 31, warp = tid >> 5;
    const int mg = lane & 7, cg = lane >> 3;
    const int c0   = warp*16 + cg*4;    // main mapping: 4 cols
    const int c0ab = warp*8  + cg*2;    // AB mapping: 2 cols

    // ---- load input [32][512] row-major swizzled into mid ----
    {
        const float4* gdat4 =
            reinterpret_cast<const float4*>(data + (size_t)b0 * S_SEQ * INDIM);
#pragma unroll
        for (int i = 0; i < (MROWS*INDIM/4)/NTHREADS; ++i) {
            int idx = tid + i*NTHREADS;
            float4 v = __ldg(gdat4 + idx);
            int lin = idx * 4;
            int m = lin >> 9;              // /512
            int k4 = (lin & (INDIM-1)) >> 2;
            unsigned off = (unsigned)((OFF_MID + m*FF)*4)
                         + (((unsigned)(k4 ^ (m & 7))) << 4);
            *reinterpret_cast<float4*>(smb + off) = v;
        }
    }

    // ---- input projection: xs = data @ in_w.T + in_b ----
    {
        float o[16];
        gemmK<256,4,false>(in_w, nullptr, INDIM, OFF_MID, FF, sm, o, tid, mg, c0);
        float4 bias = *reinterpret_cast<const float4*>(in_b + c0);
#pragma unroll
        for (int j = 0; j < 4; ++j) {
            int m = mg + 8*j;
            float4 v = make_float4(o[j*4]+bias.x, o[j*4+1]+bias.y,
                                   o[j*4+2]+bias.z, o[j*4+3]+bias.w);
            *reinterpret_cast<float4*>(smb + sw4(OFF_XS, m, HID, c0)) = v;
        }
    }
    __syncthreads();

    // ---------------- 6 layers ----------------
    for (int l = 0; l < NLAYER; ++l) {
        const float* ng = norm_g + l*HID;
        const float* nb = norm_b + l*HID;

        layer_norm2<true>(sm, OFF_XS, OFF_YS, ng, nb, tid);
        // gate = sigmoid(y @ gate_w.T + gate_b)  (gemmK lead barrier covers ys)
        float gv[16];
        {
            float o[16];
            gemmK<256,4,false>(gate_w + l*HID*HID, nullptr, HID, OFF_YS, HID, sm, o, tid, mg, c0);
            float4 bias = *reinterpret_cast<const float4*>(gate_b + l*HID + c0);
#pragma unroll
            for (int j = 0; j < 4; ++j) {
                int m = mg + 8*j;
                float4 v;
                v.x = 1.0f/(1.0f + expf(-(o[j*4]  +bias.x)));
                v.y = 1.0f/(1.0f + expf(-(o[j*4+1]+bias.y)));
                v.z = 1.0f/(1.0f + expf(-(o[j*4+2]+bias.z)));
                v.w = 1.0f/(1.0f + expf(-(o[j*4+3]+bias.w)));
                gv[j*4]=v.x; gv[j*4+1]=v.y; gv[j*4+2]=v.z; gv[j*4+3]=v.w;
                *reinterpret_cast<float4*>(smb + sw4(OFF_GS, m, HID, c0)) = v;
            }
        }
        // dt = y @ D_w.T + D_b ; xs += dt * (1 - g)
        {
            float o[16];
            gemmK<256,4,false>(D_w + l*HID*HID, nullptr, HID, OFF_YS, HID, sm, o, tid, mg, c0);
            float4 bias = *reinterpret_cast<const float4*>(D_b + l*HID + c0);
#pragma unroll
            for (int j = 0; j < 4; ++j) {
                int m = mg + 8*j;
                unsigned offx = sw4(OFF_XS, m, HID, c0);
                float4 x = *reinterpret_cast<const float4*>(smb + offx);
                x.x += (o[j*4]  +bias.x)*(1.0f-gv[j*4]);
                x.y += (o[j*4+1]+bias.y)*(1.0f-gv[j*4+1]);
                x.z += (o[j*4+2]+bias.z)*(1.0f-gv[j*4+2]);
                x.w += (o[j*4+3]+bias.w)*(1.0f-gv[j*4+3]);
                *reinterpret_cast<float4*>(smb + offx) = x;
            }
        }
        // a = tanh(y @ A_w.T), bt = y @ B_w.T  (combined 128 cols, 2 per thread)
        {
            float o[8];
            gemmK<128,2,true>(A_w + l*DSTATE*HID, B_w + l*DSTATE*HID,
                              HID, OFF_YS, HID, sm, o, tid, mg, c0ab);
            bool isA = (c0ab < DSTATE);
            int d0 = isA ? c0ab : (c0ab - DSTATE);
            int base = isA ? OFF_AT : OFF_BT;
#pragma unroll
            for (int j = 0; j < 4; ++j) {
                int m = mg + 8*j;
                float2 v;
                if (isA) { v.x = tanhf(o[j*2]); v.y = tanhf(o[j*2+1]); }
                else     { v.x = o[j*2];        v.y = o[j*2+1]; }
                unsigned off = (unsigned)((base + m*DSTATE)*4)
                             + (((unsigned)((d0 >> 2) ^ (m & 7))) << 4)
                             + ((unsigned)(d0 & 3) << 2);
                *reinterpret_cast<float2*>(smb + off) = v;
            }
        }
        __syncthreads();

        // scan: h = a*h + bt over s, in place into at (becomes hs)
        if (tid < BT*DSTATE) {
            int e = tid >> 6, d = tid & (DSTATE-1);
            float h = 0.f;
#pragma unroll
            for (int s = 0; s < S_SEQ; ++s) {
                int m = e*S_SEQ + s;
                unsigned off = (unsigned)((OFF_AT + m*DSTATE)*4)
                             + (((unsigned)((d >> 2) ^ (m & 7))) << 4)
                             + ((unsigned)(d & 3) << 2);
                float a = *reinterpret_cast<const float*>(smb + off);
                float b = *reinterpret_cast<const float*>(smb + off + (OFF_BT-OFF_AT)*4);
                h = a*h + b;
                *reinterpret_cast<float*>(smb + off) = h;
            }
        }
        __syncthreads();

        // ys = hs @ C_w.T ; xs += ys * g
        {
            float o[16];
            gemmK<256,4,false>(C_w + l*HID*DSTATE, nullptr, DSTATE, OFF_AT, DSTATE, sm, o, tid, mg, c0);
#pragma unroll
            for (int j = 0; j < 4; ++j) {
                int m = mg + 8*j;
                unsigned offx = sw4(OFF_XS, m, HID, c0);
                float4 x = *reinterpret_cast<const float4*>(smb + offx);
                x.x += o[j*4]  *gv[j*4];
                x.y += o[j*4+1]*gv[j*4+1];
                x.z += o[j*4+2]*gv[j*4+2];
                x.w += o[j*4+3]*gv[j*4+3];
                *reinterpret_cast<float4*>(smb + offx) = x;
            }
        }
        __syncthreads();

        // FFN
        layer_norm2<true>(sm, OFF_XS, OFF_YS, ng, nb, tid);
        // mid = gelu(y @ w1.T + b1), two 256-col passes
#pragma unroll
        for (int pass = 0; pass < 2; ++pass) {
            float o[16];
            gemmK<256,4,false>(ffn_w1 + l*FF*HID + pass*256*HID, nullptr, HID,
                               OFF_YS, HID, sm, o, tid, mg, c0);
            float4 bias = *reinterpret_cast<const float4*>(ffn_b1 + l*FF + pass*256 + c0);
#pragma unroll
            for (int j = 0; j < 4; ++j) {
                int m = mg + 8*j;
                float4 v;
                v.x = gelu_exact(o[j*4]  +bias.x);
                v.y = gelu_exact(o[j*4+1]+bias.y);
                v.z = gelu_exact(o[j*4+2]+bias.z);
                v.w = gelu_exact(o[j*4+3]+bias.w);
                *reinterpret_cast<float4*>(smb + sw4(OFF_MID, m, FF, pass*256 + c0)) = v;
            }
        }
        // xs += mid @ w2.T + b2  (gemmK lead barrier covers mid)
        {
            float o[16];
            gemmK<256,4,false>(ffn_w2 + l*HID*FF, nullptr, FF, OFF_MID, FF, sm, o, tid, mg, c0);
            float4 bias = *reinterpret_cast<const float4*>(ffn_b2 + l*HID + c0);
#pragma unroll
            for (int j = 0; j < 4; ++j) {
                int m = mg + 8*j;
                unsigned offx = sw4(OFF_XS, m, HID, c0);
                float4 x = *reinterpret_cast<const float4*>(smb + offx);
                x.x += o[j*4]  +bias.x;
                x.y += o[j*4+1]+bias.y;
                x.z += o[j*4+2]+bias.z;
                x.w += o[j*4+3]+bias.w;
                *reinterpret_cast<float4*>(smb + offx) = x;
            }
        }
        __syncthreads();
    }

    // ---------------- head ----------------
    layer_norm2<false>(sm, OFF_XS, OFF_GS, fln_g, fln_b, tid);  // gs linear
    __syncthreads();

    float* scores = red;            // [BT][16] (slots 0..14 used)
    float* wts    = red + 32;       // [BT][16]
    float* ov     = red + 64;       // [BT][HID]
    float* rr     = ov + BT*HID;    // [BT][128]
    float* zz     = rr + BT*128;    // [BT][NCLS]
    float* lse    = zz + BT*NCLS;   // [BT]

    {   // attention scores: warp w handles neighbor s=w+1 for both elements
        if (warp < 15) {
            for (int e = 0; e < BT; ++e) {
                const float* y0  = gs + (e*S_SEQ)*HID;
                const float* ysn = gs + (e*S_SEQ + warp + 1)*HID;
                float ssum = 0.f;
                for (int i = lane; i < HID; i += 32)
                    ssum += y0[i]*attn_w[i] + ysn[i]*attn_w[HID + i];
#pragma unroll
                for (int o = 16; o >= 1; o >>= 1)
                    ssum += __shfl_xor_sync(0xffffffffu, ssum, o);
                if (lane == 0) scores[e*16 + warp] = ssum + attn_b[0];
            }
        }
    }
    __syncthreads();
    if (tid < BT) {  // softmax over 15 neighbors
        int e = tid;
        float mx = -1e30f;
        for (int s = 0; s < 15; ++s) mx = fmaxf(mx, scores[e*16 + s]);
        float sum = 0.f;
        for (int s = 0; s < 15; ++s) sum += expf(scores[e*16 + s] - mx);
        float inv = 1.0f / sum;
        for (int s = 0; s < 15; ++s) wts[e*16 + s] = expf(scores[e*16 + s] - mx) * inv;
    }
    __syncthreads();
    {   // out_vec = node + sum_s nbr[s]*w[s]
        int e = tid >> 8, h = tid & 255;
        float v = gs[(e*S_SEQ)*HID + h];
#pragma unroll
        for (int s = 1; s < S_SEQ; ++s)
            v += gs[(e*S_SEQ + s)*HID + h] * wts[e*16 + s - 1];
        ov[e*HID + h] = v;
    }
    __syncthreads();
    if (tid < BT*128) {  // fc1 + relu
        int e = tid >> 7, j = tid & 127;
        const float* w = out_w + j*HID;
        float acc = out_b[j];
        for (int h = 0; h < HID; ++h) acc += ov[e*HID + h] * w[h];
        rr[e*128 + j] = fmaxf(acc, 0.f);
    }
    __syncthreads();
    if (tid < BT*NCLS) {  // classifier
        int e = tid / NCLS, cc = tid % NCLS;
        const float* w = cls_w + cc*128;
        float acc = cls_b[cc];
        for (int j = 0; j < 128; ++j) acc += rr[e*128 + j] * w[j];
        zz[e*NCLS + cc] = acc;
    }
    __syncthreads();
    if (tid < BT) {  // logsumexp
        int e = tid;
        float mx = -1e30f;
        for (int cc = 0; cc < NCLS; ++cc) mx = fmaxf(mx, zz[e*NCLS + cc]);
        float sum = 0.f;
        for (int cc = 0; cc < NCLS; ++cc) sum += expf(zz[e*NCLS + cc] - mx);
        lse[e] = mx + logf(sum);
    }
    __syncthreads();
    if (tid < BT*NCLS) {
        int e = tid / NCLS, cc = tid % NCLS;
        out[(size_t)(b0 + e)*NCLS + cc] = zz[e*NCLS + cc] - lse[e];
    }
}

extern "C" void kernel_launch(void* const* d_in, const int* in_sizes, int n_in,
                              void* d_out, int out_size)
{
    const float* data   = (const float*)d_in[0];
    const float* in_w   = (const float*)d_in[1];
    const float* in_b   = (const float*)d_in[2];
    const float* norm_g = (const float*)d_in[3];
    const float* norm_b = (const float*)d_in[4];
    const float* A_w    = (const float*)d_in[5];
    const float* B_w    = (const float*)d_in[6];
    const float* C_w    = (const float*)d_in[7];
    const float* D_w    = (const float*)d_in[8];
    const float* D_b    = (const float*)d_in[9];
    const float* gate_w = (const float*)d_in[10];
    const float* gate_b = (const float*)d_in[11];
    const float* ffn_w1 = (const float*)d_in[12];
    const float* ffn_b1 = (const float*)d_in[13];
    const float* ffn_w2 = (const float*)d_in[14];
    const float* ffn_b2 = (const float*)d_in[15];
    const float* fln_g  = (const float*)d_in[16];
    const float* fln_b  = (const float*)d_in[17];
    const float* out_w  = (const float*)d_in[18];
    const float* out_b  = (const float*)d_in[19];
    const float* cls_w  = (const float*)d_in[20];
    const float* cls_b  = (const float*)d_in[21];
    const float* attn_w = (const float*)d_in[22];
    const float* attn_b = (const float*)d_in[23];
    float* out = (float*)d_out;

    int Btotal = in_sizes[0] / (S_SEQ * INDIM);
    int grid = Btotal / BT;

    cudaFuncSetAttribute(mamba_fused_kernel,
                         cudaFuncAttributeMaxDynamicSharedMemorySize,
                         SMEM_FLOATS * (int)sizeof(float));

    mamba_fused_kernel<<<grid, NTHREADS, SMEM_FLOATS * sizeof(float)>>>(
        data, in_w, in_b, norm_g, norm_b, A_w, B_w, C_w, D_w, D_b,
        gate_w, gate_b, ffn_w1, ffn_b1, ffn_w2, ffn_b2,
        fln_g, fln_b, out_w, out_b, cls_w, cls_b, attn_w, attn_b, out);
}

// round 10
// speedup vs baseline: 3.2106x; 1.9168x over previous
#include <cuda_runtime.h>
#include <cuda_bf16.h>
#include <math.h>

#define S_SEQ   16
#define HID     256
#define INDIM   512
#define DSTATE  64
#define NLAYER  6
#define NCLS    40
#define FF      512
#define EPSV    1e-5f
#define BT      2
#define MROWS   32
#define NTHREADS 512

// ---------------- smem byte offsets ----------------
#define XSB   0u          // fp32 [32][256] residual, swizzled
#define YHB   32768u      // bf16 [32][256] LN-out hi
#define YLB   49152u      // bf16 lo
#define MHB   65536u      // bf16 [32][512] data/ffn-mid hi; fp32 head GS alias
#define MLB   98304u      // bf16 lo
#define WHB   131072u     // staged weights (hi then lo), up to 32KB
#define ATB   163840u     // fp32 [32][64] a / (scan in) swizzled
#define BTB   172032u     // fp32 [32][64] bt
#define HHB   180224u     // bf16 [32][64] hs hi
#define HLB   184320u     // bf16 lo
#define REDB  188416u     // fp32 head scratch
#define SMEM_BYTES 192512u

// ---------------- prepacked weights (uint4 units) ----------------
#define PW_INW  0
#define PW_GATE 32768
#define PW_D    131072
#define PW_AB   229376
#define PW_C    278528
#define PW_W1A  303104
#define PW_W1B  401408
#define PW_W2   499712
#define PW_TOTAL 696320
__device__ uint4 g_wbuf[PW_TOTAL];

__device__ __forceinline__ void f2bf2(float x, unsigned short &h, unsigned short &l) {
    __nv_bfloat16 hb = __float2bfloat16(x);
    h = __bfloat16_as_ushort(hb);
    l = __bfloat16_as_ushort(__float2bfloat16(x - __bfloat162float(hb)));
}
__device__ __forceinline__ unsigned lds32(const char* smb, unsigned off) {
    return *reinterpret_cast<const unsigned*>(smb + off);
}
__device__ __forceinline__ void mma_bf16(float* d, const unsigned* a, unsigned b0, unsigned b1) {
    asm volatile(
        "mma.sync.aligned.m16n8k16.row.col.f32.bf16.bf16.f32 "
        "{%0,%1,%2,%3}, {%4,%5,%6,%7}, {%8,%9}, {%0,%1,%2,%3};"
        : "+f"(d[0]), "+f"(d[1]), "+f"(d[2]), "+f"(d[3])
        : "r"(a[0]), "r"(a[1]), "r"(a[2]), "r"(a[3]), "r"(b0), "r"(b1));
}
__device__ __forceinline__ float gelu_exact(float x) {
    return 0.5f * x * (1.0f + erff(x * 0.70710678118654752f));
}
__device__ __forceinline__ unsigned f32off(unsigned base, int r, int rsB, int c) {
    return base + (unsigned)(r*rsB)
         + ((((unsigned)(c >> 2)) ^ ((unsigned)r & 7u)) << 4) + ((unsigned)(c & 3) << 2);
}

// ---------------- weight conversion kernel ----------------
// dst layout per layer: chunks (K/32); per chunk: hi block (NCOLSdst*4 uint4,
// index r*4+p with p = logicalUnit ^ ((r>>1)&3)), then lo block.
__global__ void convert_weights_k(const float* __restrict__ src, int srcLayerStride,
                                  uint4* __restrict__ dst, int K, int nRows, int rowOff,
                                  int NCOLSdst, int nl)
{
    int perLayer = (K/32) * nRows * 8;
    int total = nl * perLayer;
    for (int i = blockIdx.x*blockDim.x + threadIdx.x; i < total;
         i += gridDim.x*blockDim.x) {
        int layer = i / perLayer;
        int rem   = i - layer*perLayer;
        int perChunk = nRows * 8;
        int chunk = rem / perChunk;
        int rem2  = rem - chunk*perChunk;
        int plane = rem2 / (nRows*4);
        int rem3  = rem2 - plane*(nRows*4);
        int rl = rem3 >> 2, p = rem3 & 3;
        int r  = rl + rowOff;
        int kb = chunk*32 + 8*(p ^ ((r >> 1) & 3));
        const float* s = src + (size_t)layer*srcLayerStride + (size_t)rl*K + kb;
        float4 v0 = *reinterpret_cast<const float4*>(s);
        float4 v1 = *reinterpret_cast<const float4*>(s + 4);
        unsigned short h[8], l[8];
        f2bf2(v0.x,h[0],l[0]); f2bf2(v0.y,h[1],l[1]); f2bf2(v0.z,h[2],l[2]); f2bf2(v0.w,h[3],l[3]);
        f2bf2(v1.x,h[4],l[4]); f2bf2(v1.y,h[5],l[5]); f2bf2(v1.z,h[6],l[6]); f2bf2(v1.w,h[7],l[7]);
        const unsigned short* q = plane ? l : h;
        uint4 o;
        o.x = (unsigned)q[0] | ((unsigned)q[1] << 16);
        o.y = (unsigned)q[2] | ((unsigned)q[3] << 16);
        o.z = (unsigned)q[4] | ((unsigned)q[5] << 16);
        o.w = (unsigned)q[6] | ((unsigned)q[7] << 16);
        dst[((size_t)layer*(K/32) + chunk)*(NCOLSdst*8) + plane*(NCOLSdst*4) + r*4 + p] = o;
    }
}

// ---------------- bf16x2 tensor-core GEMM ----------------
// acc[t*4+i] += X[m][k]*W[c][k]; warp tile 16 x TC*8; m16n8k16 fragments.
// X: bf16 hi plane at aHiB (row stride RS bytes), lo at +aLoD, swizzled (k>>3)^(r&7).
// wsrc: prepacked layer base. ALL 512 threads call (barriers inside).
template<int NCOLS, int TC>
__device__ __forceinline__ void mma_gemm(const uint4* __restrict__ wsrc,
                                         int K, unsigned aHiB, unsigned aLoD, unsigned RS,
                                         char* __restrict__ smb, float* __restrict__ acc,
                                         int tid, int RB, int CB)
{
    const int lane = tid & 31;
    const int gr = lane >> 2, ct = lane & 3;
    constexpr int PFU = NCOLS / 64;
    constexpr unsigned WLOD = (unsigned)NCOLS * 64u;
    const int r0 = RB + gr;
    const unsigned sw  = (unsigned)(r0 & 7);
    const unsigned rb0 = aHiB + (unsigned)r0 * RS + ((unsigned)ct << 2);
    const unsigned rb1 = rb0 + 8u * RS;
    unsigned wbase[TC], wsz[TC];
#pragma unroll
    for (int t = 0; t < TC; ++t) {
        int c = CB + t*8 + gr;
        wbase[t] = WHB + (unsigned)(c * 64) + ((unsigned)ct << 2);
        wsz[t]   = ((unsigned)c >> 1) & 3u;
    }
    uint4 pf[PFU];
#pragma unroll
    for (int t = 0; t < PFU; ++t) pf[t] = __ldg(wsrc + tid + t*NTHREADS);

    const int nch = K >> 5;
    for (int c0 = 0; c0 < nch; ++c0) {
        __syncthreads();                      // prior ws consumers / X producers done
        uint4* wsm = reinterpret_cast<uint4*>(smb + WHB);
#pragma unroll
        for (int t = 0; t < PFU; ++t) wsm[tid + t*NTHREADS] = pf[t];
        __syncthreads();
        if (c0 + 1 < nch) {
            const uint4* ns = wsrc + (size_t)(c0+1)*(NCOLS*8);
#pragma unroll
            for (int t = 0; t < PFU; ++t) pf[t] = __ldg(ns + tid + t*NTHREADS);
        }
#pragma unroll
        for (int sc = 0; sc < 2; ++sc) {
            unsigned u0 = (unsigned)(c0*4 + 2*sc);
            unsigned ah[4], al[4], o;
            o = rb0 + (((u0     ) ^ sw) << 4); ah[0]=lds32(smb,o); al[0]=lds32(smb,o+aLoD);
            o = rb1 + (((u0     ) ^ sw) << 4); ah[1]=lds32(smb,o); al[1]=lds32(smb,o+aLoD);
            o = rb0 + (((u0 + 1u) ^ sw) << 4); ah[2]=lds32(smb,o); al[2]=lds32(smb,o+aLoD);
            o = rb1 + (((u0 + 1u) ^ sw) << 4); ah[3]=lds32(smb,o); al[3]=lds32(smb,o+aLoD);
            unsigned ub = (unsigned)(2*sc);
#pragma unroll
            for (int t = 0; t < TC; ++t) {
                unsigned ob0 = wbase[t] + (((ub     ) ^ wsz[t]) << 4);
                unsigned ob1 = wbase[t] + (((ub + 1u) ^ wsz[t]) << 4);
                unsigned bh0 = lds32(smb, ob0),        bh1 = lds32(smb, ob1);
                unsigned bl0 = lds32(smb, ob0 + WLOD), bl1 = lds32(smb, ob1 + WLOD);
                mma_bf16(acc + 4*t, ah, bh0, bh1);
                mma_bf16(acc + 4*t, al, bh0, bh1);
                mma_bf16(acc + 4*t, ah, bl0, bl1);
            }
        }
    }
}

// LayerNorm of fp32 xs (swizzled). PLANES: write bf16 hi/lo at YHB/YLB (swizzled);
// else fp32 linear at MHB.
template<bool PLANES>
__device__ __forceinline__ void layer_norm_p(char* __restrict__ smb,
                                             const float* __restrict__ gw,
                                             const float* __restrict__ bw, int tid)
{
    int warp = tid >> 5, lane = tid & 31;
    int m   = warp*2 + (lane >> 4);
    int sub = lane & 15;
    unsigned swm = (unsigned)(m & 7);
    unsigned rb = XSB + (unsigned)(m * 1024);
    float v[16];
#pragma unroll
    for (int i = 0; i < 4; ++i) {
        unsigned u = (unsigned)(sub*4 + i);
        float4 t = *reinterpret_cast<const float4*>(smb + rb + ((u ^ swm) << 4));
        v[4*i] = t.x; v[4*i+1] = t.y; v[4*i+2] = t.z; v[4*i+3] = t.w;
    }
    float s = 0.f;
#pragma unroll
    for (int i = 0; i < 16; ++i) s += v[i];
#pragma unroll
    for (int o = 8; o >= 1; o >>= 1) s += __shfl_xor_sync(0xffffffffu, s, o);
    float mean = s * (1.0f/HID);
    float q = 0.f;
#pragma unroll
    for (int i = 0; i < 16; ++i) { float d = v[i] - mean; q += d*d; }
#pragma unroll
    for (int o = 8; o >= 1; o >>= 1) q += __shfl_xor_sync(0xffffffffu, q, o);
    float rstd = rsqrtf(q * (1.0f/HID) + EPSV);
    int h0 = sub * 16;
    float y[16];
#pragma unroll
    for (int i = 0; i < 16; ++i)
        y[i] = (v[i] - mean) * rstd * gw[h0+i] + bw[h0+i];
    if (PLANES) {
        unsigned short hh[16], ll[16];
#pragma unroll
        for (int i = 0; i < 16; ++i) f2bf2(y[i], hh[i], ll[i]);
#pragma unroll
        for (int half = 0; half < 2; ++half) {
            const unsigned short* hs = hh + half*8;
            const unsigned short* ls = ll + half*8;
            uint4 hp, lp;
            hp.x = (unsigned)hs[0] | ((unsigned)hs[1] << 16);
            hp.y = (unsigned)hs[2] | ((unsigned)hs[3] << 16);
            hp.z = (unsigned)hs[4] | ((unsigned)hs[5] << 16);
            hp.w = (unsigned)hs[6] | ((unsigned)hs[7] << 16);
            lp.x = (unsigned)ls[0] | ((unsigned)ls[1] << 16);
            lp.y = (unsigned)ls[2] | ((unsigned)ls[3] << 16);
            lp.z = (unsigned)ls[4] | ((unsigned)ls[5] << 16);
            lp.w = (unsigned)ls[6] | ((unsigned)ls[7] << 16);
            unsigned u = (unsigned)(sub*2 + half);
            unsigned off = YHB + (unsigned)(m * 512) + ((u ^ swm) << 4);
            *reinterpret_cast<uint4*>(smb + off) = hp;
            *reinterpret_cast<uint4*>(smb + off + (YLB - YHB)) = lp;
        }
    } else {
        unsigned wb = MHB + (unsigned)(m * 1024) + (unsigned)(h0 * 4);
#pragma unroll
        for (int i = 0; i < 4; ++i)
            *reinterpret_cast<float4*>(smb + wb + i*16) =
                make_float4(y[4*i], y[4*i+1], y[4*i+2], y[4*i+3]);
    }
}

__global__ void __launch_bounds__(NTHREADS, 1)
mamba_fused_kernel(const float* __restrict__ data,
                   const float* __restrict__ in_b,
                   const float* __restrict__ norm_g,const float* __restrict__ norm_b,
                   const float* __restrict__ D_b,
                   const float* __restrict__ gate_b,
                   const float* __restrict__ ffn_b1,const float* __restrict__ ffn_b2,
                   const float* __restrict__ fln_g, const float* __restrict__ fln_b,
                   const float* __restrict__ out_w, const float* __restrict__ out_b,
                   const float* __restrict__ cls_w, const float* __restrict__ cls_b,
                   const float* __restrict__ attn_w,const float* __restrict__ attn_b,
                   float* __restrict__ out)
{
    extern __shared__ char smb[];
    const int tid = threadIdx.x;
    const int b0  = blockIdx.x * BT;
    const int warp = tid >> 5, lane = tid & 31;
    const int gr = lane >> 2, ct = lane & 3;
    const int RBm = (warp >> 3) * 16;
    const int CBm = (warp & 7) * 32;
    const int CBab = (warp & 7) * 16;
    const int r0 = RBm + gr, r1 = r0 + 8;

    // ---- input [32][512] -> bf16 hi/lo planes at MHB/MLB (swizzled) ----
    {
        const float4* gdat4 =
            reinterpret_cast<const float4*>(data + (size_t)b0 * S_SEQ * INDIM);
#pragma unroll
        for (int i = 0; i < (MROWS*INDIM/4)/NTHREADS; ++i) {
            int idx = tid + i*NTHREADS;
            float4 v = __ldg(gdat4 + idx);
            int lin = idx * 4;
            int m = lin >> 9;
            int k = lin & (INDIM-1);
            unsigned short h0_,l0_,h1_,l1_,h2_,l2_,h3_,l3_;
            f2bf2(v.x,h0_,l0_); f2bf2(v.y,h1_,l1_); f2bf2(v.z,h2_,l2_); f2bf2(v.w,h3_,l3_);
            uint2 hp = make_uint2((unsigned)h0_ | ((unsigned)h1_ << 16),
                                  (unsigned)h2_ | ((unsigned)h3_ << 16));
            uint2 lp = make_uint2((unsigned)l0_ | ((unsigned)l1_ << 16),
                                  (unsigned)l2_ | ((unsigned)l3_ << 16));
            unsigned off = MHB + (unsigned)(m * 1024)
                         + ((((unsigned)(k >> 3)) ^ ((unsigned)m & 7u)) << 4)
                         + (((unsigned)(k >> 2) & 1u) << 3);
            *reinterpret_cast<uint2*>(smb + off) = hp;
            *reinterpret_cast<uint2*>(smb + off + (MLB - MHB)) = lp;
        }
    }

    // ---- input projection ----
    {
        float acc[16];
#pragma unroll
        for (int i = 0; i < 16; ++i) acc[i] = 0.f;
        mma_gemm<256,4>(g_wbuf + PW_INW, INDIM, MHB, MLB-MHB, 1024, smb, acc, tid, RBm, CBm);
#pragma unroll
        for (int t = 0; t < 4; ++t) {
            int cb = CBm + t*8 + 2*ct;
            float2 b = *reinterpret_cast<const float2*>(in_b + cb);
            *reinterpret_cast<float2*>(smb + f32off(XSB, r0, 1024, cb)) =
                make_float2(acc[4*t]   + b.x, acc[4*t+1] + b.y);
            *reinterpret_cast<float2*>(smb + f32off(XSB, r1, 1024, cb)) =
                make_float2(acc[4*t+2] + b.x, acc[4*t+3] + b.y);
        }
    }
    __syncthreads();

    // ---------------- 6 layers ----------------
    for (int l = 0; l < NLAYER; ++l) {
        layer_norm_p<true>(smb, norm_g + l*HID, norm_b + l*HID, tid);

        float gv[16];
        {   // gate
            float acc[16];
#pragma unroll
            for (int i = 0; i < 16; ++i) acc[i] = 0.f;
            mma_gemm<256,4>(g_wbuf + PW_GATE + (size_t)l*16384, HID, YHB, YLB-YHB, 512,
                            smb, acc, tid, RBm, CBm);
#pragma unroll
            for (int t = 0; t < 4; ++t) {
                int cb = CBm + t*8 + 2*ct;
                float2 b = *reinterpret_cast<const float2*>(gate_b + l*HID + cb);
                gv[4*t]   = 1.0f/(1.0f + expf(-(acc[4*t]   + b.x)));
                gv[4*t+1] = 1.0f/(1.0f + expf(-(acc[4*t+1] + b.y)));
                gv[4*t+2] = 1.0f/(1.0f + expf(-(acc[4*t+2] + b.x)));
                gv[4*t+3] = 1.0f/(1.0f + expf(-(acc[4*t+3] + b.y)));
            }
        }
        {   // dt ; xs += dt*(1-g)
            float acc[16];
#pragma unroll
            for (int i = 0; i < 16; ++i) acc[i] = 0.f;
            mma_gemm<256,4>(g_wbuf + PW_D + (size_t)l*16384, HID, YHB, YLB-YHB, 512,
                            smb, acc, tid, RBm, CBm);
#pragma unroll
            for (int t = 0; t < 4; ++t) {
                int cb = CBm + t*8 + 2*ct;
                float2 b = *reinterpret_cast<const float2*>(D_b + l*HID + cb);
                unsigned o0 = f32off(XSB, r0, 1024, cb), o1 = f32off(XSB, r1, 1024, cb);
                float2 x0 = *reinterpret_cast<const float2*>(smb + o0);
                float2 x1 = *reinterpret_cast<const float2*>(smb + o1);
                x0.x += (acc[4*t]   + b.x)*(1.0f - gv[4*t]);
                x0.y += (acc[4*t+1] + b.y)*(1.0f - gv[4*t+1]);
                x1.x += (acc[4*t+2] + b.x)*(1.0f - gv[4*t+2]);
                x1.y += (acc[4*t+3] + b.y)*(1.0f - gv[4*t+3]);
                *reinterpret_cast<float2*>(smb + o0) = x0;
                *reinterpret_cast<float2*>(smb + o1) = x1;
            }
        }
        {   // a = tanh(yA), bt = yB  (128 cols, warp tile 16x16)
            float acc[8];
#pragma unroll
            for (int i = 0; i < 8; ++i) acc[i] = 0.f;
            mma_gemm<128,2>(g_wbuf + PW_AB + (size_t)l*8192, HID, YHB, YLB-YHB, 512,
                            smb, acc, tid, RBm, CBab);
#pragma unroll
            for (int t = 0; t < 2; ++t) {
                int cab = CBab + t*8 + 2*ct;
                if (cab < DSTATE) {
                    *reinterpret_cast<float2*>(smb + f32off(ATB, r0, 256, cab)) =
                        make_float2(tanhf(acc[4*t]), tanhf(acc[4*t+1]));
                    *reinterpret_cast<float2*>(smb + f32off(ATB, r1, 256, cab)) =
                        make_float2(tanhf(acc[4*t+2]), tanhf(acc[4*t+3]));
                } else {
                    int dd = cab - DSTATE;
                    *reinterpret_cast<float2*>(smb + f32off(BTB, r0, 256, dd)) =
                        make_float2(acc[4*t], acc[4*t+1]);
                    *reinterpret_cast<float2*>(smb + f32off(BTB, r1, 256, dd)) =
                        make_float2(acc[4*t+2], acc[4*t+3]);
                }
            }
        }
        __syncthreads();

        // scan -> hs bf16 planes
        if (tid < BT*DSTATE) {
            int e = tid >> 6, d = tid & (DSTATE-1);
            float h = 0.f;
#pragma unroll
            for (int s = 0; s < S_SEQ; ++s) {
                int m = e*S_SEQ + s;
                unsigned ao = f32off(ATB, m, 256, d);
                float a = *reinterpret_cast<const float*>(smb + ao);
                float b = *reinterpret_cast<const float*>(smb + ao + (BTB - ATB));
                h = a*h + b;
                unsigned short hh, hl;
                f2bf2(h, hh, hl);
                unsigned ho = HHB + (unsigned)(m*128)
                            + ((((unsigned)(d >> 3)) ^ ((unsigned)m & 7u)) << 4)
                            + ((unsigned)(d & 7) << 1);
                *reinterpret_cast<unsigned short*>(smb + ho) = hh;
                *reinterpret_cast<unsigned short*>(smb + ho + (HLB - HHB)) = hl;
            }
        }
        __syncthreads();

        {   // ys = hs @ C.T ; xs += ys*g
            float acc[16];
#pragma unroll
            for (int i = 0; i < 16; ++i) acc[i] = 0.f;
            mma_gemm<256,4>(g_wbuf + PW_C + (size_t)l*4096, DSTATE, HHB, HLB-HHB, 128,
                            smb, acc, tid, RBm, CBm);
#pragma unroll
            for (int t = 0; t < 4; ++t) {
                int cb = CBm + t*8 + 2*ct;
                unsigned o0 = f32off(XSB, r0, 1024, cb), o1 = f32off(XSB, r1, 1024, cb);
                float2 x0 = *reinterpret_cast<const float2*>(smb + o0);
                float2 x1 = *reinterpret_cast<const float2*>(smb + o1);
                x0.x += acc[4*t]  *gv[4*t];   x0.y += acc[4*t+1]*gv[4*t+1];
                x1.x += acc[4*t+2]*gv[4*t+2]; x1.y += acc[4*t+3]*gv[4*t+3];
                *reinterpret_cast<float2*>(smb + o0) = x0;
                *reinterpret_cast<float2*>(smb + o1) = x1;
            }
        }
        __syncthreads();

        // FFN
        layer_norm_p<true>(smb, norm_g + l*HID, norm_b + l*HID, tid);
#pragma unroll
        for (int pass = 0; pass < 2; ++pass) {
            float acc[16];
#pragma unroll
            for (int i = 0; i < 16; ++i) acc[i] = 0.f;
            const uint4* w = g_wbuf + (pass ? PW_W1B : PW_W1A) + (size_t)l*16384;
            mma_gemm<256,4>(w, HID, YHB, YLB-YHB, 512, smb, acc, tid, RBm, CBm);
#pragma unroll
            for (int t = 0; t < 4; ++t) {
                int cb = CBm + t*8 + 2*ct;
                float2 b = *reinterpret_cast<const float2*>(ffn_b1 + l*FF + pass*256 + cb);
                float v0 = gelu_exact(acc[4*t]   + b.x);
                float v1 = gelu_exact(acc[4*t+1] + b.y);
                float v2 = gelu_exact(acc[4*t+2] + b.x);
                float v3 = gelu_exact(acc[4*t+3] + b.y);
                int k = pass*256 + cb;
                unsigned short h0_,l0_,h1_,l1_;
                f2bf2(v0,h0_,l0_); f2bf2(v1,h1_,l1_);
                unsigned base0 = MHB + (unsigned)(r0*1024)
                             + ((((unsigned)(k >> 3)) ^ ((unsigned)r0 & 7u)) << 4)
                             + ((unsigned)(k & 7) << 1);
                *reinterpret_cast<unsigned*>(smb + base0) =
                    (unsigned)h0_ | ((unsigned)h1_ << 16);
                *reinterpret_cast<unsigned*>(smb + base0 + (MLB - MHB)) =
                    (unsigned)l0_ | ((unsigned)l1_ << 16);
                f2bf2(v2,h0_,l0_); f2bf2(v3,h1_,l1_);
                unsigned base1 = MHB + (unsigned)(r1*1024)
                             + ((((unsigned)(k >> 3)) ^ ((unsigned)r1 & 7u)) << 4)
                             + ((unsigned)(k & 7) << 1);
                *reinterpret_cast<unsigned*>(smb + base1) =
                    (unsigned)h0_ | ((unsigned)h1_ << 16);
                *reinterpret_cast<unsigned*>(smb + base1 + (MLB - MHB)) =
                    (unsigned)l0_ | ((unsigned)l1_ << 16);
            }
        }
        {   // xs += mid @ w2.T + b2
            float acc[16];
#pragma unroll
            for (int i = 0; i < 16; ++i) acc[i] = 0.f;
            mma_gemm<256,4>(g_wbuf + PW_W2 + (size_t)l*32768, FF, MHB, MLB-MHB, 1024,
                            smb, acc, tid, RBm, CBm);
#pragma unroll
            for (int t = 0; t < 4; ++t) {
                int cb = CBm + t*8 + 2*ct;
                float2 b = *reinterpret_cast<const float2*>(ffn_b2 + l*HID + cb);
                unsigned o0 = f32off(XSB, r0, 1024, cb), o1 = f32off(XSB, r1, 1024, cb);
                float2 x0 = *reinterpret_cast<const float2*>(smb + o0);
                float2 x1 = *reinterpret_cast<const float2*>(smb + o1);
                x0.x += acc[4*t]   + b.x;  x0.y += acc[4*t+1] + b.y;
                x1.x += acc[4*t+2] + b.x;  x1.y += acc[4*t+3] + b.y;
                *reinterpret_cast<float2*>(smb + o0) = x0;
                *reinterpret_cast<float2*>(smb + o1) = x1;
            }
        }
        __syncthreads();
    }

    // ---------------- head ----------------
    layer_norm_p<false>(smb, fln_g, fln_b, tid);   // fp32 linear at MHB
    __syncthreads();

    float* gs  = reinterpret_cast<float*>(smb + MHB);
    float* red = reinterpret_cast<float*>(smb + REDB);
    float* scores = red;
    float* wts    = red + 32;
    float* ov     = red + 64;
    float* rr     = ov + BT*HID;
    float* zz     = rr + BT*128;
    float* lse    = zz + BT*NCLS;

    if (warp < 15) {
        for (int e = 0; e < BT; ++e) {
            const float* y0  = gs + (e*S_SEQ)*HID;
            const float* ysn = gs + (e*S_SEQ + warp + 1)*HID;
            float ssum = 0.f;
            for (int i = lane; i < HID; i += 32)
                ssum += y0[i]*attn_w[i] + ysn[i]*attn_w[HID + i];
#pragma unroll
            for (int o = 16; o >= 1; o >>= 1)
                ssum += __shfl_xor_sync(0xffffffffu, ssum, o);
            if (lane == 0) scores[e*16 + warp] = ssum + attn_b[0];
        }
    }
    __syncthreads();
    if (tid < BT) {
        int e = tid;
        float mx = -1e30f;
        for (int s = 0; s < 15; ++s) mx = fmaxf(mx, scores[e*16 + s]);
        float sum = 0.f;
        for (int s = 0; s < 15; ++s) sum += expf(scores[e*16 + s] - mx);
        float inv = 1.0f / sum;
        for (int s = 0; s < 15; ++s) wts[e*16 + s] = expf(scores[e*16 + s] - mx) * inv;
    }
    __syncthreads();
    {
        int e = tid >> 8, h = tid & 255;
        float v = gs[(e*S_SEQ)*HID + h];
#pragma unroll
        for (int s = 1; s < S_SEQ; ++s)
            v += gs[(e*S_SEQ + s)*HID + h] * wts[e*16 + s - 1];
        ov[e*HID + h] = v;
    }
    __syncthreads();
    if (tid < BT*128) {
        int e = tid >> 7, j = tid & 127;
        const float* w = out_w + j*HID;
        float acc = out_b[j];
        for (int h = 0; h < HID; ++h) acc += ov[e*HID + h] * w[h];
        rr[e*128 + j] = fmaxf(acc, 0.f);
    }
    __syncthreads();
    if (tid < BT*NCLS) {
        int e = tid / NCLS, cc = tid % NCLS;
        const float* w = cls_w + cc*128;
        float acc = cls_b[cc];
        for (int j = 0; j < 128; ++j) acc += rr[e*128 + j] * w[j];
        zz[e*NCLS + cc] = acc;
    }
    __syncthreads();
    if (tid < BT) {
        int e = tid;
        float mx = -1e30f;
        for (int cc = 0; cc < NCLS; ++cc) mx = fmaxf(mx, zz[e*NCLS + cc]);
        float sum = 0.f;
        for (int cc = 0; cc < NCLS; ++cc) sum += expf(zz[e*NCLS + cc] - mx);
        lse[e] = mx + logf(sum);
    }
    __syncthreads();
    if (tid < BT*NCLS) {
        int e = tid / NCLS, cc = tid % NCLS;
        out[(size_t)(b0 + e)*NCLS + cc] = zz[e*NCLS + cc] - lse[e];
    }
}

extern "C" void kernel_launch(void* const* d_in, const int* in_sizes, int n_in,
                              void* d_out, int out_size)
{
    const float* data   = (const float*)d_in[0];
    const float* in_w   = (const float*)d_in[1];
    const float* in_b   = (const float*)d_in[2];
    const float* norm_g = (const float*)d_in[3];
    const float* norm_b = (const float*)d_in[4];
    const float* A_w    = (const float*)d_in[5];
    const float* B_w    = (const float*)d_in[6];
    const float* C_w    = (const float*)d_in[7];
    const float* D_w    = (const float*)d_in[8];
    const float* D_b    = (const float*)d_in[9];
    const float* gate_w = (const float*)d_in[10];
    const float* gate_b = (const float*)d_in[11];
    const float* ffn_w1 = (const float*)d_in[12];
    const float* ffn_b1 = (const float*)d_in[13];
    const float* ffn_w2 = (const float*)d_in[14];
    const float* ffn_b2 = (const float*)d_in[15];
    const float* fln_g  = (const float*)d_in[16];
    const float* fln_b  = (const float*)d_in[17];
    const float* out_w  = (const float*)d_in[18];
    const float* out_b  = (const float*)d_in[19];
    const float* cls_w  = (const float*)d_in[20];
    const float* cls_b  = (const float*)d_in[21];
    const float* attn_w = (const float*)d_in[22];
    const float* attn_b = (const float*)d_in[23];
    float* out = (float*)d_out;

    uint4* wbuf = nullptr;
    cudaGetSymbolAddress((void**)&wbuf, g_wbuf);

    const int CB = 256, GB = 1024;
    // src, srcLayerStride, dst, K, nRows, rowOff, NCOLSdst, nl
    convert_weights_k<<<GB,CB>>>(in_w,   0,        wbuf + PW_INW,  INDIM, 256, 0, 256, 1);
    convert_weights_k<<<GB,CB>>>(gate_w, HID*HID,  wbuf + PW_GATE, HID,   256, 0, 256, NLAYER);
    convert_weights_k<<<GB,CB>>>(D_w,    HID*HID,  wbuf + PW_D,    HID,   256, 0, 256, NLAYER);
    convert_weights_k<<<GB,CB>>>(A_w,    DSTATE*HID, wbuf + PW_AB, HID,   64,  0, 128, NLAYER);
    convert_weights_k<<<GB,CB>>>(B_w,    DSTATE*HID, wbuf + PW_AB, HID,   64,  64,128, NLAYER);
    convert_weights_k<<<GB,CB>>>(C_w,    HID*DSTATE, wbuf + PW_C,  DSTATE,256, 0, 256, NLAYER);
    convert_weights_k<<<GB,CB>>>(ffn_w1, FF*HID,   wbuf + PW_W1A,  HID,   256, 0, 256, NLAYER);
    convert_weights_k<<<GB,CB>>>(ffn_w1 + 256*HID, FF*HID, wbuf + PW_W1B, HID, 256, 0, 256, NLAYER);
    convert_weights_k<<<GB,CB>>>(ffn_w2, HID*FF,   wbuf + PW_W2,   FF,    256, 0, 256, NLAYER);

    int Btotal = in_sizes[0] / (S_SEQ * INDIM);
    int grid = Btotal / BT;

    cudaFuncSetAttribute(mamba_fused_kernel,
                         cudaFuncAttributeMaxDynamicSharedMemorySize, SMEM_BYTES);

    mamba_fused_kernel<<<grid, NTHREADS, SMEM_BYTES>>>(
        data, in_b, norm_g, norm_b, D_b, gate_b, ffn_b1, ffn_b2,
        fln_g, fln_b, out_w, out_b, cls_w, cls_b, attn_w, attn_b, out);
}

// round 16
// speedup vs baseline: 3.3392x; 1.0401x over previous
#include <cuda_runtime.h>
#include <cuda_bf16.h>
#include <math.h>

#define S_SEQ   16
#define HID     256
#define INDIM   512
#define DSTATE  64
#define NLAYER  6
#define NCLS    40
#define FF      512
#define EPSV    1e-5f
#define BT      2
#define MROWS   32
#define NTHREADS 512

// ---------------- smem byte offsets ----------------
#define XSB   0u          // fp32 [32][256] residual, swizzled
#define YHB   32768u      // bf16 [32][256] LN-out hi
#define YLB   49152u      // bf16 lo
#define MHB   65536u      // bf16 [32][512] data/ffn-mid hi; fp32 head GS alias
#define MLB   98304u      // bf16 lo
#define WHB   131072u     // staged weights buf0 (hi then lo), 32KB; buf1 at +32768
#define ATB   196608u     // fp32 [32][64] a (scan in) swizzled
#define BTB   204800u     // fp32 [32][64] bt
#define HHB   212992u     // bf16 [32][64] hs hi
#define HLB   217088u     // bf16 lo
#define REDB  221184u     // fp32 head scratch
#define SMEM_BYTES 225280u

// ---------------- prepacked weights (uint4 units) ----------------
#define PW_INW  0
#define PW_GATE 32768
#define PW_D    131072
#define PW_AB   229376
#define PW_C    278528
#define PW_W1A  303104
#define PW_W1B  401408
#define PW_W2   499712
#define PW_TOTAL 696320
__device__ uint4 g_wbuf[PW_TOTAL];

__device__ __forceinline__ void f2bf2(float x, unsigned short &h, unsigned short &l) {
    __nv_bfloat16 hb = __float2bfloat16(x);
    h = __bfloat16_as_ushort(hb);
    l = __bfloat16_as_ushort(__float2bfloat16(x - __bfloat162float(hb)));
}
__device__ __forceinline__ unsigned lds32(const char* smb, unsigned off) {
    return *reinterpret_cast<const unsigned*>(smb + off);
}
__device__ __forceinline__ void mma_bf16(float* d, const unsigned* a, unsigned b0, unsigned b1) {
    asm volatile(
        "mma.sync.aligned.m16n8k16.row.col.f32.bf16.bf16.f32 "
        "{%0,%1,%2,%3}, {%4,%5,%6,%7}, {%8,%9}, {%0,%1,%2,%3};"
        : "+f"(d[0]), "+f"(d[1]), "+f"(d[2]), "+f"(d[3])
        : "r"(a[0]), "r"(a[1]), "r"(a[2]), "r"(a[3]), "r"(b0), "r"(b1));
}
__device__ __forceinline__ float gelu_exact(float x) {
    return 0.5f * x * (1.0f + erff(x * 0.70710678118654752f));
}
__device__ __forceinline__ unsigned f32off(unsigned base, int r, int rsB, int c) {
    return base + (unsigned)(r*rsB)
         + ((((unsigned)(c >> 2)) ^ ((unsigned)r & 7u)) << 4) + ((unsigned)(c & 3) << 2);
}

// ---------------- weight conversion kernel ----------------
// dst layout per layer: chunks (K/32); per chunk: hi block (NCOLSdst*4 uint4,
// index r*4+p with p = logicalUnit ^ ((r>>1)&3)), then lo block.
__global__ void convert_weights_k(const float* __restrict__ src, int srcLayerStride,
                                  uint4* __restrict__ dst, int K, int nRows, int rowOff,
                                  int NCOLSdst, int nl)
{
    int perLayer = (K/32) * nRows * 8;
    int total = nl * perLayer;
    for (int i = blockIdx.x*blockDim.x + threadIdx.x; i < total;
         i += gridDim.x*blockDim.x) {
        int layer = i / perLayer;
        int rem   = i - layer*perLayer;
        int perChunk = nRows * 8;
        int chunk = rem / perChunk;
        int rem2  = rem - chunk*perChunk;
        int plane = rem2 / (nRows*4);
        int rem3  = rem2 - plane*(nRows*4);
        int rl = rem3 >> 2, p = rem3 & 3;
        int r  = rl + rowOff;
        int kb = chunk*32 + 8*(p ^ ((r >> 1) & 3));
        const float* s = src + (size_t)layer*srcLayerStride + (size_t)rl*K + kb;
        float4 v0 = *reinterpret_cast<const float4*>(s);
        float4 v1 = *reinterpret_cast<const float4*>(s + 4);
        unsigned short h[8], l[8];
        f2bf2(v0.x,h[0],l[0]); f2bf2(v0.y,h[1],l[1]); f2bf2(v0.z,h[2],l[2]); f2bf2(v0.w,h[3],l[3]);
        f2bf2(v1.x,h[4],l[4]); f2bf2(v1.y,h[5],l[5]); f2bf2(v1.z,h[6],l[6]); f2bf2(v1.w,h[7],l[7]);
        const unsigned short* q = plane ? l : h;
        uint4 o;
        o.x = (unsigned)q[0] | ((unsigned)q[1] << 16);
        o.y = (unsigned)q[2] | ((unsigned)q[3] << 16);
        o.z = (unsigned)q[4] | ((unsigned)q[5] << 16);
        o.w = (unsigned)q[6] | ((unsigned)q[7] << 16);
        dst[((size_t)layer*(K/32) + chunk)*(NCOLSdst*8) + plane*(NCOLSdst*4) + r*4 + p] = o;
    }
}

// ---------------- bf16x2 tensor-core GEMM (lds32 loads + double buffer) -----
// acc[t*4+i] += X[m][k]*W[c][k]; warp tile 16 x TC*8; m16n8k16 fragments.
// X: bf16 hi plane at aHiB (row stride RS bytes), lo at +aLoD, swizzled (k>>3)^(r&7).
// Weight chunks double-buffered at WHB / WHB+32KB; one barrier per chunk; the
// next chunk's LDG issues before compute and its STS lands after compute.
// Fragment loads are byte-identical to the proven single-buffer version.
// ALL 512 threads call (barriers inside).
template<int NCOLS, int TC>
__device__ __forceinline__ void mma_gemm(const uint4* __restrict__ wsrc,
                                         int K, unsigned aHiB, unsigned aLoD, unsigned RS,
                                         char* __restrict__ smb, float* __restrict__ acc,
                                         int tid, int RB, int CB)
{
    const int lane = tid & 31;
    const int gr = lane >> 2, ct = lane & 3;
    constexpr int PFU = NCOLS / 64;
    constexpr unsigned WLOD = (unsigned)NCOLS * 64u;
    const int r0 = RB + gr;
    const unsigned sw  = (unsigned)(r0 & 7);
    const unsigned rb0 = aHiB + (unsigned)r0 * RS + ((unsigned)ct << 2);
    const unsigned rb1 = rb0 + 8u * RS;
    unsigned wbase[TC], wsz[TC];
#pragma unroll
    for (int t = 0; t < TC; ++t) {
        int c = CB + t*8 + gr;
        wbase[t] = WHB + (unsigned)(c * 64) + ((unsigned)ct << 2);
        wsz[t]   = ((unsigned)c >> 1) & 3u;
    }

    uint4 pf[PFU];
#pragma unroll
    for (int t = 0; t < PFU; ++t) pf[t] = __ldg(wsrc + tid + t*NTHREADS);
    {   // stage chunk 0 into buf0
        uint4* wsm = reinterpret_cast<uint4*>(smb + WHB);
#pragma unroll
        for (int t = 0; t < PFU; ++t) wsm[tid + t*NTHREADS] = pf[t];
    }
    __syncthreads();

    const int nch = K >> 5;
    for (int c0 = 0; c0 < nch; ++c0) {
        if (c0 + 1 < nch) {   // prefetch next chunk; lands during compute below
            const uint4* ns = wsrc + (size_t)(c0+1)*(NCOLS*8);
#pragma unroll
            for (int t = 0; t < PFU; ++t) pf[t] = __ldg(ns + tid + t*NTHREADS);
        }
        const unsigned bufx = ((unsigned)(c0 & 1)) << 15;
#pragma unroll
        for (int sc = 0; sc < 2; ++sc) {
            unsigned u0 = (unsigned)(c0*4 + 2*sc);
            unsigned ah[4], al[4], o;
            o = rb0 + (((u0     ) ^ sw) << 4); ah[0]=lds32(smb,o); al[0]=lds32(smb,o+aLoD);
            o = rb1 + (((u0     ) ^ sw) << 4); ah[1]=lds32(smb,o); al[1]=lds32(smb,o+aLoD);
            o = rb0 + (((u0 + 1u) ^ sw) << 4); ah[2]=lds32(smb,o); al[2]=lds32(smb,o+aLoD);
            o = rb1 + (((u0 + 1u) ^ sw) << 4); ah[3]=lds32(smb,o); al[3]=lds32(smb,o+aLoD);
            unsigned ub = (unsigned)(2*sc);
#pragma unroll
            for (int t = 0; t < TC; ++t) {
                unsigned ob0 = wbase[t] + (((ub     ) ^ wsz[t]) << 4) + bufx;
                unsigned ob1 = wbase[t] + (((ub + 1u) ^ wsz[t]) << 4) + bufx;
                unsigned bh0 = lds32(smb, ob0),        bh1 = lds32(smb, ob1);
                unsigned bl0 = lds32(smb, ob0 + WLOD), bl1 = lds32(smb, ob1 + WLOD);
                mma_bf16(acc + 4*t, ah, bh0, bh1);
                mma_bf16(acc + 4*t, al, bh0, bh1);
                mma_bf16(acc + 4*t, ah, bl0, bl1);
            }
        }
        if (c0 + 1 < nch) {   // store next chunk into the other buffer
            uint4* wsm = reinterpret_cast<uint4*>(smb + WHB + ((((unsigned)(c0+1) & 1u)) << 15));
#pragma unroll
            for (int t = 0; t < PFU; ++t) wsm[tid + t*NTHREADS] = pf[t];
        }
        __syncthreads();
    }
}

// LayerNorm of fp32 xs (swizzled). PLANES: write bf16 hi/lo at YHB/YLB (swizzled);
// else fp32 linear at MHB.
template<bool PLANES>
__device__ __forceinline__ void layer_norm_p(char* __restrict__ smb,
                                             const float* __restrict__ gw,
                                             const float* __restrict__ bw, int tid)
{
    int warp = tid >> 5, lane = tid & 31;
    int m   = warp*2 + (lane >> 4);
    int sub = lane & 15;
    unsigned swm = (unsigned)(m & 7);
    unsigned rb = XSB + (unsigned)(m * 1024);
    float v[16];
#pragma unroll
    for (int i = 0; i < 4; ++i) {
        unsigned u = (unsigned)(sub*4 + i);
        float4 t = *reinterpret_cast<const float4*>(smb + rb + ((u ^ swm) << 4));
        v[4*i] = t.x; v[4*i+1] = t.y; v[4*i+2] = t.z; v[4*i+3] = t.w;
    }
    float s = 0.f;
#pragma unroll
    for (int i = 0; i < 16; ++i) s += v[i];
#pragma unroll
    for (int o = 8; o >= 1; o >>= 1) s += __shfl_xor_sync(0xffffffffu, s, o);
    float mean = s * (1.0f/HID);
    float q = 0.f;
#pragma unroll
    for (int i = 0; i < 16; ++i) { float d = v[i] - mean; q += d*d; }
#pragma unroll
    for (int o = 8; o >= 1; o >>= 1) q += __shfl_xor_sync(0xffffffffu, q, o);
    float rstd = rsqrtf(q * (1.0f/HID) + EPSV);
    int h0 = sub * 16;
    float y[16];
#pragma unroll
    for (int i = 0; i < 16; ++i)
        y[i] = (v[i] - mean) * rstd * gw[h0+i] + bw[h0+i];
    if (PLANES) {
        unsigned short hh[16], ll[16];
#pragma unroll
        for (int i = 0; i < 16; ++i) f2bf2(y[i], hh[i], ll[i]);
#pragma unroll
        for (int half = 0; half < 2; ++half) {
            const unsigned short* hs = hh + half*8;
            const unsigned short* ls = ll + half*8;
            uint4 hp, lp;
            hp.x = (unsigned)hs[0] | ((unsigned)hs[1] << 16);
            hp.y = (unsigned)hs[2] | ((unsigned)hs[3] << 16);
            hp.z = (unsigned)hs[4] | ((unsigned)hs[5] << 16);
            hp.w = (unsigned)hs[6] | ((unsigned)hs[7] << 16);
            lp.x = (unsigned)ls[0] | ((unsigned)ls[1] << 16);
            lp.y = (unsigned)ls[2] | ((unsigned)ls[3] << 16);
            lp.z = (unsigned)ls[4] | ((unsigned)ls[5] << 16);
            lp.w = (unsigned)ls[6] | ((unsigned)ls[7] << 16);
            unsigned u = (unsigned)(sub*2 + half);
            unsigned off = YHB + (unsigned)(m * 512) + ((u ^ swm) << 4);
            *reinterpret_cast<uint4*>(smb + off) = hp;
            *reinterpret_cast<uint4*>(smb + off + (YLB - YHB)) = lp;
        }
    } else {
        unsigned wb = MHB + (unsigned)(m * 1024) + (unsigned)(h0 * 4);
#pragma unroll
        for (int i = 0; i < 4; ++i)
            *reinterpret_cast<float4*>(smb + wb + i*16) =
                make_float4(y[4*i], y[4*i+1], y[4*i+2], y[4*i+3]);
    }
}

__global__ void __launch_bounds__(NTHREADS, 1)
mamba_fused_kernel(const float* __restrict__ data,
                   const float* __restrict__ in_b,
                   const float* __restrict__ norm_g,const float* __restrict__ norm_b,
                   const float* __restrict__ D_b,
                   const float* __restrict__ gate_b,
                   const float* __restrict__ ffn_b1,const float* __restrict__ ffn_b2,
                   const float* __restrict__ fln_g, const float* __restrict__ fln_b,
                   const float* __restrict__ out_w, const float* __restrict__ out_b,
                   const float* __restrict__ cls_w, const float* __restrict__ cls_b,
                   const float* __restrict__ attn_w,const float* __restrict__ attn_b,
                   float* __restrict__ out)
{
    extern __shared__ char smb[];
    const int tid = threadIdx.x;
    const int b0  = blockIdx.x * BT;
    const int warp = tid >> 5, lane = tid & 31;
    const int ct = lane & 3;
    const int RBm = (warp >> 3) * 16;
    const int CBm = (warp & 7) * 32;
    const int CBab = (warp & 7) * 16;
    const int r0 = RBm + (lane >> 2), r1 = r0 + 8;

    // ---- input [32][512] -> bf16 hi/lo planes at MHB/MLB (swizzled) ----
    {
        const float4* gdat4 =
            reinterpret_cast<const float4*>(data + (size_t)b0 * S_SEQ * INDIM);
#pragma unroll
        for (int i = 0; i < (MROWS*INDIM/4)/NTHREADS; ++i) {
            int idx = tid + i*NTHREADS;
            float4 v = __ldg(gdat4 + idx);
            int lin = idx * 4;
            int m = lin >> 9;
            int k = lin & (INDIM-1);
            unsigned short h0_,l0_,h1_,l1_,h2_,l2_,h3_,l3_;
            f2bf2(v.x,h0_,l0_); f2bf2(v.y,h1_,l1_); f2bf2(v.z,h2_,l2_); f2bf2(v.w,h3_,l3_);
            uint2 hp = make_uint2((unsigned)h0_ | ((unsigned)h1_ << 16),
                                  (unsigned)h2_ | ((unsigned)h3_ << 16));
            uint2 lp = make_uint2((unsigned)l0_ | ((unsigned)l1_ << 16),
                                  (unsigned)l2_ | ((unsigned)l3_ << 16));
            unsigned off = MHB + (unsigned)(m * 1024)
                         + ((((unsigned)(k >> 3)) ^ ((unsigned)m & 7u)) << 4)
                         + (((unsigned)(k >> 2) & 1u) << 3);
            *reinterpret_cast<uint2*>(smb + off) = hp;
            *reinterpret_cast<uint2*>(smb + off + (MLB - MHB)) = lp;
        }
    }

    // ---- input projection ----
    {
        float acc[16];
#pragma unroll
        for (int i = 0; i < 16; ++i) acc[i] = 0.f;
        mma_gemm<256,4>(g_wbuf + PW_INW, INDIM, MHB, MLB-MHB, 1024, smb, acc, tid, RBm, CBm);
#pragma unroll
        for (int t = 0; t < 4; ++t) {
            int cb = CBm + t*8 + 2*ct;
            float2 b = *reinterpret_cast<const float2*>(in_b + cb);
            *reinterpret_cast<float2*>(smb + f32off(XSB, r0, 1024, cb)) =
                make_float2(acc[4*t]   + b.x, acc[4*t+1] + b.y);
            *reinterpret_cast<float2*>(smb + f32off(XSB, r1, 1024, cb)) =
                make_float2(acc[4*t+2] + b.x, acc[4*t+3] + b.y);
        }
    }
    __syncthreads();

    // ---------------- 6 layers ----------------
    for (int l = 0; l < NLAYER; ++l) {
        layer_norm_p<true>(smb, norm_g + l*HID, norm_b + l*HID, tid);

        float gv[16];
        {   // gate
            float acc[16];
#pragma unroll
            for (int i = 0; i < 16; ++i) acc[i] = 0.f;
            mma_gemm<256,4>(g_wbuf + PW_GATE + (size_t)l*16384, HID, YHB, YLB-YHB, 512,
                            smb, acc, tid, RBm, CBm);
#pragma unroll
            for (int t = 0; t < 4; ++t) {
                int cb = CBm + t*8 + 2*ct;
                float2 b = *reinterpret_cast<const float2*>(gate_b + l*HID + cb);
                gv[4*t]   = 1.0f/(1.0f + expf(-(acc[4*t]   + b.x)));
                gv[4*t+1] = 1.0f/(1.0f + expf(-(acc[4*t+1] + b.y)));
                gv[4*t+2] = 1.0f/(1.0f + expf(-(acc[4*t+2] + b.x)));
                gv[4*t+3] = 1.0f/(1.0f + expf(-(acc[4*t+3] + b.y)));
            }
        }
        {   // dt ; xs += dt*(1-g)
            float acc[16];
#pragma unroll
            for (int i = 0; i < 16; ++i) acc[i] = 0.f;
            mma_gemm<256,4>(g_wbuf + PW_D + (size_t)l*16384, HID, YHB, YLB-YHB, 512,
                            smb, acc, tid, RBm, CBm);
#pragma unroll
            for (int t = 0; t < 4; ++t) {
                int cb = CBm + t*8 + 2*ct;
                float2 b = *reinterpret_cast<const float2*>(D_b + l*HID + cb);
                unsigned o0 = f32off(XSB, r0, 1024, cb), o1 = f32off(XSB, r1, 1024, cb);
                float2 x0 = *reinterpret_cast<const float2*>(smb + o0);
                float2 x1 = *reinterpret_cast<const float2*>(smb + o1);
                x0.x += (acc[4*t]   + b.x)*(1.0f - gv[4*t]);
                x0.y += (acc[4*t+1] + b.y)*(1.0f - gv[4*t+1]);
                x1.x += (acc[4*t+2] + b.x)*(1.0f - gv[4*t+2]);
                x1.y += (acc[4*t+3] + b.y)*(1.0f - gv[4*t+3]);
                *reinterpret_cast<float2*>(smb + o0) = x0;
                *reinterpret_cast<float2*>(smb + o1) = x1;
            }
        }
        {   // a = tanh(yA), bt = yB  (128 cols, warp tile 16x16)
            float acc[8];
#pragma unroll
            for (int i = 0; i < 8; ++i) acc[i] = 0.f;
            mma_gemm<128,2>(g_wbuf + PW_AB + (size_t)l*8192, HID, YHB, YLB-YHB, 512,
                            smb, acc, tid, RBm, CBab);
#pragma unroll
            for (int t = 0; t < 2; ++t) {
                int cab = CBab + t*8 + 2*ct;
                if (cab < DSTATE) {
                    *reinterpret_cast<float2*>(smb + f32off(ATB, r0, 256, cab)) =
                        make_float2(tanhf(acc[4*t]), tanhf(acc[4*t+1]));
                    *reinterpret_cast<float2*>(smb + f32off(ATB, r1, 256, cab)) =
                        make_float2(tanhf(acc[4*t+2]), tanhf(acc[4*t+3]));
                } else {
                    int dd = cab - DSTATE;
                    *reinterpret_cast<float2*>(smb + f32off(BTB, r0, 256, dd)) =
                        make_float2(acc[4*t], acc[4*t+1]);
                    *reinterpret_cast<float2*>(smb + f32off(BTB, r1, 256, dd)) =
                        make_float2(acc[4*t+2], acc[4*t+3]);
                }
            }
        }
        __syncthreads();

        // scan -> hs bf16 planes
        if (tid < BT*DSTATE) {
            int e = tid >> 6, d = tid & (DSTATE-1);
            float h = 0.f;
#pragma unroll
            for (int s = 0; s < S_SEQ; ++s) {
                int m = e*S_SEQ + s;
                unsigned ao = f32off(ATB, m, 256, d);
                float a = *reinterpret_cast<const float*>(smb + ao);
                float b = *reinterpret_cast<const float*>(smb + ao + (BTB - ATB));
                h = a*h + b;
                unsigned short hh, hl;
                f2bf2(h, hh, hl);
                unsigned ho = HHB + (unsigned)(m*128)
                            + ((((unsigned)(d >> 3)) ^ ((unsigned)m & 7u)) << 4)
                            + ((unsigned)(d & 7) << 1);
                *reinterpret_cast<unsigned short*>(smb + ho) = hh;
                *reinterpret_cast<unsigned short*>(smb + ho + (HLB - HHB)) = hl;
            }
        }
        __syncthreads();

        {   // ys = hs @ C.T ; xs += ys*g
            float acc[16];
#pragma unroll
            for (int i = 0; i < 16; ++i) acc[i] = 0.f;
            mma_gemm<256,4>(g_wbuf + PW_C + (size_t)l*4096, DSTATE, HHB, HLB-HHB, 128,
                            smb, acc, tid, RBm, CBm);
#pragma unroll
            for (int t = 0; t < 4; ++t) {
                int cb = CBm + t*8 + 2*ct;
                unsigned o0 = f32off(XSB, r0, 1024, cb), o1 = f32off(XSB, r1, 1024, cb);
                float2 x0 = *reinterpret_cast<const float2*>(smb + o0);
                float2 x1 = *reinterpret_cast<const float2*>(smb + o1);
                x0.x += acc[4*t]  *gv[4*t];   x0.y += acc[4*t+1]*gv[4*t+1];
                x1.x += acc[4*t+2]*gv[4*t+2]; x1.y += acc[4*t+3]*gv[4*t+3];
                *reinterpret_cast<float2*>(smb + o0) = x0;
                *reinterpret_cast<float2*>(smb + o1) = x1;
            }
        }
        __syncthreads();

        // FFN
        layer_norm_p<true>(smb, norm_g + l*HID, norm_b + l*HID, tid);
#pragma unroll
        for (int pass = 0; pass < 2; ++pass) {
            float acc[16];
#pragma unroll
            for (int i = 0; i < 16; ++i) acc[i] = 0.f;
            const uint4* w = g_wbuf + (pass ? PW_W1B : PW_W1A) + (size_t)l*16384;
            mma_gemm<256,4>(w, HID, YHB, YLB-YHB, 512, smb, acc, tid, RBm, CBm);
#pragma unroll
            for (int t = 0; t < 4; ++t) {
                int cb = CBm + t*8 + 2*ct;
                float2 b = *reinterpret_cast<const float2*>(ffn_b1 + l*FF + pass*256 + cb);
                float v0 = gelu_exact(acc[4*t]   + b.x);
                float v1 = gelu_exact(acc[4*t+1] + b.y);
                float v2 = gelu_exact(acc[4*t+2] + b.x);
                float v3 = gelu_exact(acc[4*t+3] + b.y);
                int k = pass*256 + cb;
                unsigned short h0_,l0_,h1_,l1_;
                f2bf2(v0,h0_,l0_); f2bf2(v1,h1_,l1_);
                unsigned base0 = MHB + (unsigned)(r0*1024)
                             + ((((unsigned)(k >> 3)) ^ ((unsigned)r0 & 7u)) << 4)
                             + ((unsigned)(k & 7) << 1);
                *reinterpret_cast<unsigned*>(smb + base0) =
                    (unsigned)h0_ | ((unsigned)h1_ << 16);
                *reinterpret_cast<unsigned*>(smb + base0 + (MLB - MHB)) =
                    (unsigned)l0_ | ((unsigned)l1_ << 16);
                f2bf2(v2,h0_,l0_); f2bf2(v3,h1_,l1_);
                unsigned base1 = MHB + (unsigned)(r1*1024)
                             + ((((unsigned)(k >> 3)) ^ ((unsigned)r1 & 7u)) << 4)
                             + ((unsigned)(k & 7) << 1);
                *reinterpret_cast<unsigned*>(smb + base1) =
                    (unsigned)h0_ | ((unsigned)h1_ << 16);
                *reinterpret_cast<unsigned*>(smb + base1 + (MLB - MHB)) =
                    (unsigned)l0_ | ((unsigned)l1_ << 16);
            }
        }
        {   // xs += mid @ w2.T + b2
            float acc[16];
#pragma unroll
            for (int i = 0; i < 16; ++i) acc[i] = 0.f;
            mma_gemm<256,4>(g_wbuf + PW_W2 + (size_t)l*32768, FF, MHB, MLB-MHB, 1024,
                            smb, acc, tid, RBm, CBm);
#pragma unroll
            for (int t = 0; t < 4; ++t) {
                int cb = CBm + t*8 + 2*ct;
                float2 b = *reinterpret_cast<const float2*>(ffn_b2 + l*HID + cb);
                unsigned o0 = f32off(XSB, r0, 1024, cb), o1 = f32off(XSB, r1, 1024, cb);
                float2 x0 = *reinterpret_cast<const float2*>(smb + o0);
                float2 x1 = *reinterpret_cast<const float2*>(smb + o1);
                x0.x += acc[4*t]   + b.x;  x0.y += acc[4*t+1] + b.y;
                x1.x += acc[4*t+2] + b.x;  x1.y += acc[4*t+3] + b.y;
                *reinterpret_cast<float2*>(smb + o0) = x0;
                *reinterpret_cast<float2*>(smb + o1) = x1;
            }
        }
        __syncthreads();
    }

    // ---------------- head ----------------
    layer_norm_p<false>(smb, fln_g, fln_b, tid);   // fp32 linear at MHB
    __syncthreads();

    float* gs  = reinterpret_cast<float*>(smb + MHB);
    float* red = reinterpret_cast<float*>(smb + REDB);
    float* scores = red;
    float* wts    = red + 32;
    float* ov     = red + 64;
    float* rr     = ov + BT*HID;
    float* zz     = rr + BT*128;
    float* lse    = zz + BT*NCLS;

    if (warp < 15) {
        for (int e = 0; e < BT; ++e) {
            const float* y0  = gs + (e*S_SEQ)*HID;
            const float* ysn = gs + (e*S_SEQ + warp + 1)*HID;
            float ssum = 0.f;
            for (int i = lane; i < HID; i += 32)
                ssum += y0[i]*attn_w[i] + ysn[i]*attn_w[HID + i];
#pragma unroll
            for (int o = 16; o >= 1; o >>= 1)
                ssum += __shfl_xor_sync(0xffffffffu, ssum, o);
            if (lane == 0) scores[e*16 + warp] = ssum + attn_b[0];
        }
    }
    __syncthreads();
    if (tid < BT) {
        int e = tid;
        float mx = -1e30f;
        for (int s = 0; s < 15; ++s) mx = fmaxf(mx, scores[e*16 + s]);
        float sum = 0.f;
        for (int s = 0; s < 15; ++s) sum += expf(scores[e*16 + s] - mx);
        float inv = 1.0f / sum;
        for (int s = 0; s < 15; ++s) wts[e*16 + s] = expf(scores[e*16 + s] - mx) * inv;
    }
    __syncthreads();
    {
        int e = tid >> 8, h = tid & 255;
        float v = gs[(e*S_SEQ)*HID + h];
#pragma unroll
        for (int s = 1; s < S_SEQ; ++s)
            v += gs[(e*S_SEQ + s)*HID + h] * wts[e*16 + s - 1];
        ov[e*HID + h] = v;
    }
    __syncthreads();
    if (tid < BT*128) {
        int e = tid >> 7, j = tid & 127;
        const float* w = out_w + j*HID;
        float acc = out_b[j];
        for (int h = 0; h < HID; ++h) acc += ov[e*HID + h] * w[h];
        rr[e*128 + j] = fmaxf(acc, 0.f);
    }
    __syncthreads();
    if (tid < BT*NCLS) {
        int e = tid / NCLS, cc = tid % NCLS;
        const float* w = cls_w + cc*128;
        float acc = cls_b[cc];
        for (int j = 0; j < 128; ++j) acc += rr[e*128 + j] * w[j];
        zz[e*NCLS + cc] = acc;
    }
    __syncthreads();
    if (tid < BT) {
        int e = tid;
        float mx = -1e30f;
        for (int cc = 0; cc < NCLS; ++cc) mx = fmaxf(mx, zz[e*NCLS + cc]);
        float sum = 0.f;
        for (int cc = 0; cc < NCLS; ++cc) sum += expf(zz[e*NCLS + cc] - mx);
        lse[e] = mx + logf(sum);
    }
    __syncthreads();
    if (tid < BT*NCLS) {
        int e = tid / NCLS, cc = tid % NCLS;
        out[(size_t)(b0 + e)*NCLS + cc] = zz[e*NCLS + cc] - lse[e];
    }
}

extern "C" void kernel_launch(void* const* d_in, const int* in_sizes, int n_in,
                              void* d_out, int out_size)
{
    const float* data   = (const float*)d_in[0];
    const float* in_w   = (const float*)d_in[1];
    const float* in_b   = (const float*)d_in[2];
    const float* norm_g = (const float*)d_in[3];
    const float* norm_b = (const float*)d_in[4];
    const float* A_w    = (const float*)d_in[5];
    const float* B_w    = (const float*)d_in[6];
    const float* C_w    = (const float*)d_in[7];
    const float* D_w    = (const float*)d_in[8];
    const float* D_b    = (const float*)d_in[9];
    const float* gate_w = (const float*)d_in[10];
    const float* gate_b = (const float*)d_in[11];
    const float* ffn_w1 = (const float*)d_in[12];
    const float* ffn_b1 = (const float*)d_in[13];
    const float* ffn_w2 = (const float*)d_in[14];
    const float* ffn_b2 = (const float*)d_in[15];
    const float* fln_g  = (const float*)d_in[16];
    const float* fln_b  = (const float*)d_in[17];
    const float* out_w  = (const float*)d_in[18];
    const float* out_b  = (const float*)d_in[19];
    const float* cls_w  = (const float*)d_in[20];
    const float* cls_b  = (const float*)d_in[21];
    const float* attn_w = (const float*)d_in[22];
    const float* attn_b = (const float*)d_in[23];
    float* out = (float*)d_out;

    uint4* wbuf = nullptr;
    cudaGetSymbolAddress((void**)&wbuf, g_wbuf);

    const int CB = 256, GB = 1024;
    convert_weights_k<<<GB,CB>>>(in_w,   0,        wbuf + PW_INW,  INDIM, 256, 0, 256, 1);
    convert_weights_k<<<GB,CB>>>(gate_w, HID*HID,  wbuf + PW_GATE, HID,   256, 0, 256, NLAYER);
    convert_weights_k<<<GB,CB>>>(D_w,    HID*HID,  wbuf + PW_D,    HID,   256, 0, 256, NLAYER);
    convert_weights_k<<<GB,CB>>>(A_w,    DSTATE*HID, wbuf + PW_AB, HID,   64,  0, 128, NLAYER);
    convert_weights_k<<<GB,CB>>>(B_w,    DSTATE*HID, wbuf + PW_AB, HID,   64,  64,128, NLAYER);
    convert_weights_k<<<GB,CB>>>(C_w,    HID*DSTATE, wbuf + PW_C,  DSTATE,256, 0, 256, NLAYER);
    convert_weights_k<<<GB,CB>>>(ffn_w1, FF*HID,   wbuf + PW_W1A,  HID,   256, 0, 256, NLAYER);
    convert_weights_k<<<GB,CB>>>(ffn_w1 + 256*HID, FF*HID, wbuf + PW_W1B, HID, 256, 0, 256, NLAYER);
    convert_weights_k<<<GB,CB>>>(ffn_w2, HID*FF,   wbuf + PW_W2,   FF,    256, 0, 256, NLAYER);

    int Btotal = in_sizes[0] / (S_SEQ * INDIM);
    int grid = Btotal / BT;

    cudaFuncSetAttribute(mamba_fused_kernel,
                         cudaFuncAttributeMaxDynamicSharedMemorySize, SMEM_BYTES);

    mamba_fused_kernel<<<grid, NTHREADS, SMEM_BYTES>>>(
        data, in_b, norm_g, norm_b, D_b, gate_b, ffn_b1, ffn_b2,
        fln_g, fln_b, out_w, out_b, cls_w, cls_b, attn_w, attn_b, out);
}